// round 13
// baseline (speedup 1.0000x reference)
#include <cuda_runtime.h>
#include <math.h>
#include <stdint.h>

#define B_      256
#define L_      16
#define H_      256
#define V_      5000
#define P_      4
#define NPG_    150
#define DEG_    4
#define EPG_    (NPG_*DEG_)
#define STEPS_  4
#define OUT_    2000
#define N_      (B_*NPG_)
#define E_      (N_*DEG_)
#define BL_     (B_*L_)
#define LDLOG_  5008

// ---------------- scratch arena ----------------
static constexpr size_t SZ_C    = (size_t)(V_+1)*H_;
static constexpr size_t SZ_XW   = (size_t)BL_*H_;
static constexpr size_t SZ_LOG  = (size_t)BL_*LDLOG_;
static constexpr size_t SZ_VT   = (size_t)BL_*H_;
static constexpr size_t SZ_XG   = (size_t)BL_*4*H_;
static constexpr size_t SZ_H    = (size_t)B_*H_;
static constexpr size_t SZ_HINS = (size_t)B_*STEPS_*H_;
static constexpr size_t SZ_TR   = (size_t)N_*3*H_;
static constexpr size_t SZ_ET   = (size_t)E_*H_;

static constexpr size_t OFF_C    = 0;
static constexpr size_t OFF_XW   = OFF_C    + SZ_C;
static constexpr size_t OFF_LOG  = OFF_XW   + SZ_XW;
static constexpr size_t OFF_RM   = OFF_LOG  + SZ_LOG;
static constexpr size_t OFF_RI   = OFF_RM   + BL_;
static constexpr size_t OFF_VT   = OFF_RI   + BL_;
static constexpr size_t OFF_XG   = OFF_VT   + SZ_VT;
static constexpr size_t OFF_H    = OFF_XG   + SZ_XG;
static constexpr size_t OFF_CS   = OFF_H    + SZ_H;
static constexpr size_t OFF_H2   = OFF_CS   + SZ_H;
static constexpr size_t OFF_R    = OFF_H2   + SZ_H;
static constexpr size_t OFF_PS   = OFF_R    + SZ_HINS;
static constexpr size_t OFF_TR   = OFF_PS   + (size_t)B_*STEPS_*P_;
static constexpr size_t OFF_ET   = OFF_TR   + SZ_TR;
static constexpr size_t OFF_NS4  = OFF_ET   + SZ_ET;
static constexpr size_t OFF_ES4  = OFF_NS4  + (size_t)N_*4;
static constexpr size_t OFF_DIST = OFF_ES4  + (size_t)E_*4;
static constexpr size_t OFF_QA   = OFF_DIST + N_;
static constexpr size_t OFF_WNT  = OFF_QA   + (size_t)B_*2*H_;
static constexpr size_t OFF_VOCT = OFF_WNT  + (size_t)H_*H_;
static constexpr size_t OFF_WIHT = OFF_VOCT + (size_t)H_*LDLOG_;
static constexpr size_t OFF_WHHT = OFF_WIHT + (size_t)H_*H_;
static constexpr size_t TOTAL_SCRATCH = OFF_WHHT + (size_t)H_*H_;

__device__ __align__(16) float g_scratch[TOTAL_SCRATCH];

// ---------------- helpers ----------------
__device__ __forceinline__ float warp_sum(float v) {
    #pragma unroll
    for (int o = 16; o > 0; o >>= 1) v += __shfl_down_sync(0xffffffffu, v, o);
    return v;
}
__device__ __forceinline__ float sigmoidf_(float x) { return 1.f / (1.f + expf(-x)); }
__device__ __forceinline__ uint32_t f2tf32(float x) {
    uint32_t u;
    asm("cvt.rna.tf32.f32 %0, %1;" : "=r"(u) : "f"(x));
    return u;
}
__device__ __forceinline__ uint32_t smem_u32(const void* p) {
    uint32_t a;
    asm("{ .reg .u64 t; cvta.to.shared.u64 t, %1; cvt.u32.u64 %0, t; }" : "=r"(a) : "l"(p));
    return a;
}
__device__ __forceinline__ void cp_async16(void* sdst, const void* gsrc, bool pred) {
    uint32_t d = smem_u32(sdst);
    int sz = pred ? 16 : 0;
    asm volatile("cp.async.cg.shared.global [%0], [%1], 16, %2;"
                 :: "r"(d), "l"(gsrc), "r"(sz));
}
__device__ __forceinline__ void cp_commit() {
    asm volatile("cp.async.commit_group;" ::: "memory");
}
template<int N>
__device__ __forceinline__ void cp_wait() {
    asm volatile("cp.async.wait_group %0;" :: "n"(N) : "memory");
}
__device__ __forceinline__ void mma_tf32(float* d, const uint32_t* a, const uint32_t* b) {
    asm volatile(
        "mma.sync.aligned.m16n8k8.row.col.f32.tf32.tf32.f32 "
        "{%0,%1,%2,%3}, {%4,%5,%6,%7}, {%8,%9}, {%0,%1,%2,%3};"
        : "+f"(d[0]), "+f"(d[1]), "+f"(d[2]), "+f"(d[3])
        : "r"(a[0]), "r"(a[1]), "r"(a[2]), "r"(a[3]), "r"(b[0]), "r"(b[1]));
}

// ---------------- tf32 GEMM: CTA 128x128x32, 128 thr, warp 64x64 (2x2) ----------------
// EXPA: A'[m,k] = exp(A[m,k]-rowmax[m])*rowinv[m] (softmax fused into loader)
#define GB_M 128
#define GB_N 128
#define GB_K 32
#define GTS  36
#define GABUF (GB_M*GTS)
#define GBBUF (GB_N*GTS)
#define G_SMEM_BYTES ((2*GABUF + 2*GBBUF)*4)

template<bool EXPA>
__global__ void __launch_bounds__(128, 2)
mma_gemm_k(const float* __restrict__ A, int lda,
           const float* __restrict__ Bm, int ldb,
           float* __restrict__ C, int ldc,
           int M, int N, int K, const float* __restrict__ bias, int splitk,
           const float* __restrict__ rowmax, const float* __restrict__ rowinv)
{
    extern __shared__ float smf[];
    float* As = smf;
    float* Bs = smf + 2*GABUF;
    const int tid  = threadIdx.x;
    const int wid  = tid >> 5, lane = tid & 31;
    const int g    = lane >> 2, t4 = lane & 3;
    const int wm   = wid & 1, wn = wid >> 1;
    const int bm   = blockIdx.y * GB_M;
    const int bn   = blockIdx.x * GB_N;

    int kbeg = 0, kend = K;
    if (splitk > 1) {
        int kslen = (((K + splitk - 1) / splitk) + 3) & ~3;
        kbeg  = blockIdx.z * kslen;
        kend  = min(K, kbeg + kslen);
    }

    float acc[4][8][4];
    #pragma unroll
    for (int i = 0; i < 4; i++)
        #pragma unroll
        for (int j = 0; j < 8; j++)
            #pragma unroll
            for (int q = 0; q < 4; q++) acc[i][j][q] = 0.f;

    const int lrow = tid >> 3, lc4 = (tid & 7) << 2;

    auto issue_chunk = [&](int c) {
        int k0 = kbeg + c * GB_K;
        int buf = c & 1;
        if (EXPA) {
            // A: LDG + exp + STS (values identical to materialized softmax probs)
            float rm_c = 0.f, ri_c = 0.f;
            #pragma unroll
            for (int i = 0; i < 8; i++) {
                int row = lrow + i*16;
                int gm = bm + row, gk = k0 + lc4;
                float4 v = make_float4(0.f, 0.f, 0.f, 0.f);
                bool ok = (gm < M) && (gk < kend);
                if (ok) {
                    v = *reinterpret_cast<const float4*>(A + (size_t)gm*lda + gk);
                    rm_c = rowmax[gm]; ri_c = rowinv[gm];
                    v.x = expf(v.x - rm_c)*ri_c; v.y = expf(v.y - rm_c)*ri_c;
                    v.z = expf(v.z - rm_c)*ri_c; v.w = expf(v.w - rm_c)*ri_c;
                    // per-row partial tail inside a valid float4 cannot occur: K,kc mult of 4
                    if (gk + 3 >= kend) {
                        if (gk+1 >= kend) v.y = 0.f;
                        if (gk+2 >= kend) v.z = 0.f;
                        if (gk+3 >= kend) v.w = 0.f;
                    }
                }
                float* d = As + buf*GABUF + row*GTS + lc4;
                d[0] = v.x; d[1] = v.y; d[2] = v.z; d[3] = v.w;
            }
        } else {
            #pragma unroll
            for (int i = 0; i < 8; i++) {
                int row = lrow + i*16;
                int gm = bm + row, gk = k0 + lc4;
                cp_async16(As + buf*GABUF + row*GTS + lc4,
                           A + (size_t)gm*lda + gk, (gm < M) && (gk < kend));
            }
        }
        #pragma unroll
        for (int i = 0; i < 8; i++) {
            int row = lrow + i*16;
            int gn = bn + row, gk = k0 + lc4;
            cp_async16(Bs + buf*GBBUF + row*GTS + lc4,
                       Bm + (size_t)gn*ldb + gk, (gn < N) && (gk < kend));
        }
        cp_commit();
    };

    const int nch = (kend - kbeg + GB_K - 1) / GB_K;
    issue_chunk(0);

    for (int c = 0; c < nch; c++) {
        if (c + 1 < nch) { issue_chunk(c + 1); cp_wait<1>(); }
        else             { cp_wait<0>(); }
        __syncthreads();

        const float* Ab = As + (c & 1)*GABUF;
        const float* Bb = Bs + (c & 1)*GBBUF;
        #pragma unroll
        for (int ks = 0; ks < 4; ks++) {
            uint32_t af[4][4], bf[8][2];
            #pragma unroll
            for (int mt = 0; mt < 4; mt++) {
                int r0 = (wm*64 + mt*16 + g)*GTS + ks*8 + t4;
                af[mt][0] = f2tf32(Ab[r0]);
                af[mt][1] = f2tf32(Ab[r0 + 8*GTS]);
                af[mt][2] = f2tf32(Ab[r0 + 4]);
                af[mt][3] = f2tf32(Ab[r0 + 8*GTS + 4]);
            }
            #pragma unroll
            for (int nt = 0; nt < 8; nt++) {
                int rb = (wn*64 + nt*8 + g)*GTS + ks*8 + t4;
                bf[nt][0] = f2tf32(Bb[rb]);
                bf[nt][1] = f2tf32(Bb[rb + 4]);
            }
            #pragma unroll
            for (int mt = 0; mt < 4; mt++)
                #pragma unroll
                for (int nt = 0; nt < 8; nt++)
                    mma_tf32(acc[mt][nt], af[mt], bf[nt]);
        }
        __syncthreads();
    }

    const bool addb = (bias != nullptr) && (blockIdx.z == 0);
    #pragma unroll
    for (int mt = 0; mt < 4; mt++) {
        int row0 = bm + wm*64 + mt*16 + g;
        #pragma unroll
        for (int nt = 0; nt < 8; nt++) {
            int col0 = bn + wn*64 + nt*8 + t4*2;
            float b0v = 0.f, b1v = 0.f;
            if (addb) {
                if (col0     < N) b0v = bias[col0];
                if (col0 + 1 < N) b1v = bias[col0+1];
            }
            if (splitk > 1) {
                if (row0 < M) {
                    if (col0     < N) atomicAdd(&C[(size_t)row0*ldc + col0    ], acc[mt][nt][0] + b0v);
                    if (col0 + 1 < N) atomicAdd(&C[(size_t)row0*ldc + col0 + 1], acc[mt][nt][1] + b1v);
                }
                if (row0 + 8 < M) {
                    if (col0     < N) atomicAdd(&C[(size_t)(row0+8)*ldc + col0    ], acc[mt][nt][2] + b0v);
                    if (col0 + 1 < N) atomicAdd(&C[(size_t)(row0+8)*ldc + col0 + 1], acc[mt][nt][3] + b1v);
                }
            } else {
                if (row0 < M) {
                    if (col0     < N) C[(size_t)row0*ldc + col0    ] = acc[mt][nt][0] + b0v;
                    if (col0 + 1 < N) C[(size_t)row0*ldc + col0 + 1] = acc[mt][nt][1] + b1v;
                }
                if (row0 + 8 < M) {
                    if (col0     < N) C[(size_t)(row0+8)*ldc + col0    ] = acc[mt][nt][2] + b0v;
                    if (col0 + 1 < N) C[(size_t)(row0+8)*ldc + col0 + 1] = acc[mt][nt][3] + b1v;
                }
            }
        }
    }
}

// ---------------- tensor-core fused LSTM step ----------------
#define LB_M 64
#define LB_N 128
#define LTS  36
#define LABUF (LB_M*LTS)
#define LBBUF (LB_N*LTS)
#define L_SMEM_BYTES ((2*LABUF + 2*LBBUF)*4)

__global__ void __launch_bounds__(128, 2)
lstm_mma_k(const float* __restrict__ hin,
           float* __restrict__ hout,
           float* __restrict__ cst,
           const float* __restrict__ Xg,
           const float* __restrict__ Whh,
           const float* __restrict__ bhh,
           const int* __restrict__ lengths, int t)
{
    extern __shared__ float smf[];
    float* As = smf;
    float* Bs = smf + 2*LABUF;
    float* Cs = smf;
    const int tid = threadIdx.x;
    const int wid = tid >> 5, lane = tid & 31;
    const int g   = lane >> 2, t4 = lane & 3;
    const int wm  = wid & 1, wn = wid >> 1;
    const int hh0 = blockIdx.x * 32;
    const int bm  = blockIdx.y * LB_M;

    float acc[2][8][4];
    #pragma unroll
    for (int i = 0; i < 2; i++)
        #pragma unroll
        for (int j = 0; j < 8; j++)
            #pragma unroll
            for (int q = 0; q < 4; q++) acc[i][j][q] = 0.f;

    const int lrow = tid >> 3, lc4 = (tid & 7) << 2;

    auto issue_chunk = [&](int c) {
        int k0 = c * GB_K;
        int buf = c & 1;
        #pragma unroll
        for (int i = 0; i < 4; i++) {
            int row = lrow + i*16;
            cp_async16(As + buf*LABUF + row*LTS + lc4,
                       hin + (size_t)(bm + row)*H_ + k0 + lc4, true);
        }
        #pragma unroll
        for (int i = 0; i < 8; i++) {
            int row = lrow + i*16;
            int gn = (row >> 5)*H_ + hh0 + (row & 31);
            cp_async16(Bs + buf*LBBUF + row*LTS + lc4,
                       Whh + (size_t)gn*H_ + k0 + lc4, true);
        }
        cp_commit();
    };

    const int nch = H_ / GB_K;
    issue_chunk(0);
    for (int c = 0; c < nch; c++) {
        if (c + 1 < nch) { issue_chunk(c + 1); cp_wait<1>(); }
        else             { cp_wait<0>(); }
        __syncthreads();
        const float* Ab = As + (c & 1)*LABUF;
        const float* Bb = Bs + (c & 1)*LBBUF;
        #pragma unroll
        for (int ks = 0; ks < 4; ks++) {
            uint32_t af[2][4], bf[8][2];
            #pragma unroll
            for (int mt = 0; mt < 2; mt++) {
                int r0 = (wm*32 + mt*16 + g)*LTS + ks*8 + t4;
                af[mt][0] = f2tf32(Ab[r0]);
                af[mt][1] = f2tf32(Ab[r0 + 8*LTS]);
                af[mt][2] = f2tf32(Ab[r0 + 4]);
                af[mt][3] = f2tf32(Ab[r0 + 8*LTS + 4]);
            }
            #pragma unroll
            for (int nt = 0; nt < 8; nt++) {
                int rb = (wn*64 + nt*8 + g)*LTS + ks*8 + t4;
                bf[nt][0] = f2tf32(Bb[rb]);
                bf[nt][1] = f2tf32(Bb[rb + 4]);
            }
            #pragma unroll
            for (int mt = 0; mt < 2; mt++)
                #pragma unroll
                for (int nt = 0; nt < 8; nt++)
                    mma_tf32(acc[mt][nt], af[mt], bf[nt]);
        }
        __syncthreads();
    }

    #pragma unroll
    for (int mt = 0; mt < 2; mt++) {
        int row0 = wm*32 + mt*16 + g;
        #pragma unroll
        for (int nt = 0; nt < 8; nt++) {
            int col0 = wn*64 + nt*8 + t4*2;
            Cs[row0*132 + col0]       = acc[mt][nt][0];
            Cs[row0*132 + col0 + 1]   = acc[mt][nt][1];
            Cs[(row0+8)*132 + col0]   = acc[mt][nt][2];
            Cs[(row0+8)*132 + col0+1] = acc[mt][nt][3];
        }
    }
    __syncthreads();

    #pragma unroll
    for (int i = 0; i < 16; i++) {
        int cell = i*128 + tid;
        int b_l = cell >> 5, hh_l = cell & 31;
        int b = bm + b_l, hh = hh0 + hh_l;
        const float* xrow = Xg + (size_t)(b*L_ + t)*(4*H_);
        float gi = Cs[b_l*132 + 0*32 + hh_l] + xrow[hh]        + bhh[hh];
        float gf = Cs[b_l*132 + 1*32 + hh_l] + xrow[H_+hh]     + bhh[H_+hh];
        float gc = Cs[b_l*132 + 2*32 + hh_l] + xrow[2*H_+hh]   + bhh[2*H_+hh];
        float go = Cs[b_l*132 + 3*32 + hh_l] + xrow[3*H_+hh]   + bhh[3*H_+hh];
        size_t idx = (size_t)b*H_ + hh;
        if (t < lengths[b]) {
            float cn = sigmoidf_(gf)*cst[idx] + sigmoidf_(gi)*tanhf(gc);
            cst[idx] = cn;
            hout[idx] = sigmoidf_(go)*tanhf(cn);
        } else {
            hout[idx] = hin[idx];
        }
    }
}

// ---------------- fused decoder RNN + attention ----------------
__global__ void __launch_bounds__(256)
dec_attn_k(const float* __restrict__ Q,
           const float* __restrict__ WihT,
           const float* __restrict__ WhhT,
           const float* __restrict__ bih, const float* __restrict__ bhh,
           const float* __restrict__ Vt,
           const int* __restrict__ lengths,
           float* __restrict__ R)
{
    int b = blockIdx.x, tid = threadIdx.x;
    __shared__ float shh[H_], sQ[H_], sh[H_];
    __shared__ float sV[L_][H_];
    __shared__ float sHins[STEPS_][H_];
    __shared__ float satt[STEPS_][L_];

    shh[tid] = Q[(size_t)b*H_ + tid];
    for (int i = tid; i < L_*H_; i += 256) sV[i>>8][i&255] = Vt[(size_t)b*L_*H_ + i];
    __syncthreads();

    float acc = bih[tid];
    #pragma unroll 8
    for (int k = 0; k < H_; k++) acc = fmaf(shh[k], WihT[(size_t)k*H_ + tid], acc);
    sQ[tid] = acc;
    sh[tid] = 0.f;
    __syncthreads();

    for (int s = 0; s < STEPS_; s++) {
        float v = sQ[tid] + bhh[tid];
        #pragma unroll 8
        for (int k = 0; k < H_; k++) v = fmaf(sh[k], WhhT[(size_t)k*H_ + tid], v);
        v = fmaxf(v, 0.f);
        __syncthreads();
        sh[tid] = v;
        sHins[s][tid] = v;
        __syncthreads();
    }

    int warp = tid >> 5, lane = tid & 31;
    for (int pid = warp; pid < STEPS_*L_; pid += 8) {
        int s = pid >> 4, l = pid & 15;
        float a = 0.f;
        #pragma unroll
        for (int q = 0; q < H_/32; q++) a = fmaf(sHins[s][lane+32*q], sV[l][lane+32*q], a);
        a = warp_sum(a);
        if (lane == 0) satt[s][l] = a;
    }
    __syncthreads();
    if (tid < STEPS_) {
        int len = lengths[b];
        float m = -3.4e38f;
        for (int l = 0; l < len; l++) m = fmaxf(m, satt[tid][l]);
        float s = 0.f;
        for (int l = 0; l < len; l++) { float e = expf(satt[tid][l]-m); satt[tid][l]=e; s+=e; }
        float inv = 1.f/s;
        for (int l = 0; l < L_; l++) satt[tid][l] = (l < len) ? satt[tid][l]*inv : 0.f;
    }
    __syncthreads();
    for (int s = 0; s < STEPS_; s++) {
        float a2 = 0.f;
        #pragma unroll
        for (int l = 0; l < L_; l++) a2 = fmaf(satt[s][l], sV[l][tid], a2);
        R[((size_t)b*STEPS_ + s)*H_ + tid] = a2;
    }
}

// ---------------- small kernels ----------------
__global__ void build_c_k(const float* __restrict__ vocab, const float* __restrict__ de,
                          float* __restrict__ Cc) {
    int i = blockIdx.x*256 + threadIdx.x;
    if (i < (V_+1)*H_) Cc[i] = (i < V_*H_) ? vocab[i] : de[i - (size_t)V_*H_];
}

__global__ void transpose_wn_k(const float* __restrict__ W, float* __restrict__ WT) {
    __shared__ float t[32][33];
    int rb = blockIdx.y*32, cb = blockIdx.x*32;
    int x = threadIdx.x, y = threadIdx.y;
    for (int j = y; j < 32; j += 8) t[j][x] = W[(size_t)(rb+j)*H_ + cb + x];
    __syncthreads();
    for (int j = y; j < 32; j += 8) WT[(size_t)(cb+j)*H_ + rb + x] = t[x][j];
}

__global__ void vocab_t_k(const float* __restrict__ vocab, float* __restrict__ vt) {
    __shared__ float t[32][33];
    int vb = blockIdx.x*32, hb = blockIdx.y*32;
    int x = threadIdx.x, y = threadIdx.y;
    for (int j = y; j < 32; j += 8) {
        int v = vb + j;
        t[j][x] = (v < V_) ? vocab[(size_t)v*H_ + hb + x] : 0.f;
    }
    __syncthreads();
    for (int j = y; j < 32; j += 8) {
        int v = vb + x;
        if (v < LDLOG_) vt[(size_t)(hb+j)*LDLOG_ + v] = t[x][j];
    }
}

__global__ void zero_k(float* __restrict__ p, int n) {
    int i = blockIdx.x*256 + threadIdx.x;
    if (i < n) p[i] = 0.f;
}

// stats-only softmax: rm = rowmax, ri = 1/rowsum. LG left as raw logits.
__global__ void row_softmax_stats_k(const float* __restrict__ Lg,
                                    float* __restrict__ rm, float* __restrict__ ri) {
    int r = blockIdx.x;
    const float* row = Lg + (size_t)r*LDLOG_;
    __shared__ float red[256];
    float m = -3.4e38f;
    for (int j = threadIdx.x; j < V_+1; j += 256) m = fmaxf(m, row[j]);
    red[threadIdx.x] = m; __syncthreads();
    for (int o = 128; o > 0; o >>= 1) {
        if (threadIdx.x < o) red[threadIdx.x] = fmaxf(red[threadIdx.x], red[threadIdx.x+o]);
        __syncthreads();
    }
    float M = red[0]; __syncthreads();
    float s = 0.f;
    for (int j = threadIdx.x; j < V_+1; j += 256) s += expf(row[j] - M);
    red[threadIdx.x] = s; __syncthreads();
    for (int o = 128; o > 0; o >>= 1) {
        if (threadIdx.x < o) red[threadIdx.x] += red[threadIdx.x+o];
        __syncthreads();
    }
    if (threadIdx.x == 0) { rm[r] = M; ri[r] = 1.f/red[0]; }
}

// VT init: epsilon term w*words (the split-K Vtag GEMM then accumulates on top)
__global__ void vtag_init_k(const float* __restrict__ words, const float* __restrict__ Lg,
                            const float* __restrict__ rm, const float* __restrict__ ri,
                            float* __restrict__ Vt) {
    int i = blockIdx.x*256 + threadIdx.x;
    int r = i >> 8;
    float w = expf(Lg[(size_t)r*LDLOG_ + V_] - rm[r]) * ri[r];
    Vt[i] = w * words[i];
}

__global__ void __launch_bounds__(128)
prop_all_k(const float* __restrict__ R, const float* __restrict__ pe,
           float* __restrict__ ps4) {
    int b = blockIdx.x, s = blockIdx.y;
    int p = threadIdx.x >> 5, lane = threadIdx.x & 31;
    const float* instr = R + ((size_t)b*STEPS_ + s)*H_;
    float acc = 0.f;
    for (int h = lane; h < H_; h += 32) acc = fmaf(instr[h], pe[p*H_ + h], acc);
    acc = warp_sum(acc);
    __shared__ float s4[P_];
    if (lane == 0) s4[p] = acc;
    __syncthreads();
    if (threadIdx.x == 0) {
        float m = fmaxf(fmaxf(s4[0], s4[1]), fmaxf(s4[2], s4[3]));
        float e0 = expf(s4[0]-m), e1 = expf(s4[1]-m), e2 = expf(s4[2]-m), e3 = expf(s4[3]-m);
        float inv = 1.f/(e0+e1+e2+e3);
        float* o = ps4 + ((size_t)b*STEPS_ + s)*P_;
        o[0]=e0*inv; o[1]=e1*inv; o[2]=e2*inv; o[3]=e3*inv;
    }
}

#define NODE_BLKS (N_/8)
#define EDGE_BLKS (E_/8)
__global__ void __launch_bounds__(256)
scores_k(const float* __restrict__ Tr, const float* __restrict__ Et,
         const float* __restrict__ R, const float* __restrict__ ps4,
         const float* __restrict__ Wst, const float* __restrict__ Wrel,
         const int* __restrict__ ng, const int* __restrict__ eg,
         float* __restrict__ ns4, float* __restrict__ es4) {
    int bid = blockIdx.x;
    int warp = threadIdx.x >> 5, lane = threadIdx.x & 31;
    if (bid < NODE_BLKS) {
        int n = bid*8 + warp;
        int g = ng[n];
        const float* T = Tr + (size_t)n*3*H_;
        float t0[8], t1[8], t2[8], ws[8];
        #pragma unroll
        for (int q = 0; q < 8; q++) {
            int h = lane + 32*q;
            t0[q] = T[h]; t1[q] = T[H_+h]; t2[q] = T[2*H_+h]; ws[q] = Wst[h];
        }
        float out[STEPS_];
        #pragma unroll
        for (int s = 0; s < STEPS_; s++) {
            const float* pp = ps4 + ((size_t)g*STEPS_ + s)*P_;
            float p0 = pp[0], p1 = pp[1], p2 = pp[2];
            const float* instr = R + ((size_t)g*STEPS_ + s)*H_;
            float acc = 0.f;
            #pragma unroll
            for (int q = 0; q < 8; q++) {
                int h = lane + 32*q;
                float tv = p0*t0[q] + p1*t1[q] + p2*t2[q];
                float x = instr[h]*tv;
                float e = (x > 0.f) ? x : expm1f(x);
                acc = fmaf(e, ws[q], acc);
            }
            out[s] = warp_sum(acc);
        }
        if (lane == 0)
            *reinterpret_cast<float4*>(ns4 + (size_t)n*4) =
                make_float4(out[0], out[1], out[2], out[3]);
    } else {
        int e = (bid - NODE_BLKS)*8 + warp;
        int g = eg[e];
        const float* et = Et + (size_t)e*H_;
        float ev[8], wr[8];
        #pragma unroll
        for (int q = 0; q < 8; q++) {
            int h = lane + 32*q;
            ev[q] = et[h]; wr[q] = Wrel[h];
        }
        float out[STEPS_];
        #pragma unroll
        for (int s = 0; s < STEPS_; s++) {
            const float* instr = R + ((size_t)g*STEPS_ + s)*H_;
            float acc = 0.f;
            #pragma unroll
            for (int q = 0; q < 8; q++) {
                int h = lane + 32*q;
                float x = instr[h]*ev[q];
                float el = (x > 0.f) ? x : expm1f(x);
                acc = fmaf(el, wr[q], acc);
            }
            out[s] = warp_sum(acc);
        }
        if (lane == 0)
            *reinterpret_cast<float4*>(es4 + (size_t)e*4) =
                make_float4(out[0], out[1], out[2], out[3]);
    }
}

__global__ void __launch_bounds__(256)
graph_loop_k(const float* __restrict__ ns4, const float* __restrict__ es4,
             const float* __restrict__ ps4,
             const int* __restrict__ esrc, const int* __restrict__ edst,
             float* __restrict__ dist_out) {
    int g = blockIdx.x, tid = threadIdx.x;
    __shared__ float dist[NPG_], agg[NPG_], red[256];
    __shared__ int lsrc[EPG_], ldst[EPG_];
    __shared__ float4 ns[NPG_];

    int nbase = g*NPG_, ebase = g*EPG_;
    for (int e = tid; e < EPG_; e += 256) {
        lsrc[e] = esrc[ebase + e] - nbase;
        ldst[e] = edst[ebase + e] - nbase;
    }
    if (tid < NPG_) {
        dist[tid] = 1.f/(float)NPG_;
        ns[tid] = *reinterpret_cast<const float4*>(ns4 + (size_t)(nbase + tid)*4);
    }
    __syncthreads();

    for (int s = 0; s < STEPS_; s++) {
        if (tid < NPG_) agg[tid] = 0.f;
        __syncthreads();
        for (int e = tid; e < EPG_; e += 256) {
            float sc = es4[(size_t)(ebase + e)*4 + s];
            atomicAdd(&agg[ldst[e]], dist[lsrc[e]]*sc);
        }
        __syncthreads();

        float nsv = (tid < NPG_) ? ((const float*)&ns[tid])[s] : -3.4e38f;
        float agv = (tid < NPG_) ? agg[tid] : -3.4e38f;
        red[tid] = nsv; __syncthreads();
        for (int o = 128; o > 0; o >>= 1) { if (tid < o) red[tid] = fmaxf(red[tid], red[tid+o]); __syncthreads(); }
        float m1 = red[0]; __syncthreads();
        red[tid] = agv; __syncthreads();
        for (int o = 128; o > 0; o >>= 1) { if (tid < o) red[tid] = fmaxf(red[tid], red[tid+o]); __syncthreads(); }
        float m2 = red[0]; __syncthreads();
        float e1 = (tid < NPG_) ? expf(nsv - m1) : 0.f;
        float e2 = (tid < NPG_) ? expf(agv - m2) : 0.f;
        red[tid] = e1; __syncthreads();
        for (int o = 128; o > 0; o >>= 1) { if (tid < o) red[tid] += red[tid+o]; __syncthreads(); }
        float s1 = red[0]; __syncthreads();
        red[tid] = e2; __syncthreads();
        for (int o = 128; o > 0; o >>= 1) { if (tid < o) red[tid] += red[tid+o]; __syncthreads(); }
        float s2 = red[0]; __syncthreads();
        if (tid < NPG_) {
            float r = ps4[((size_t)g*STEPS_ + s)*P_ + 3];
            dist[tid] = r*(e2/s2) + (1.f - r)*(e1/s1);
        }
        __syncthreads();
    }
    if (tid < NPG_) dist_out[nbase + tid] = dist[tid];
}

__global__ void final_agg_qa_k(const float* __restrict__ na, const float* __restrict__ ps4,
                               const float* __restrict__ dist, const float* __restrict__ Q,
                               float* __restrict__ QA) {
    int g = blockIdx.x, h = threadIdx.x;
    const float* pp = ps4 + ((size_t)g*STEPS_ + (STEPS_-1))*P_;
    float p0 = pp[0], p1 = pp[1], p2 = pp[2];
    float acc = 0.f;
    for (int i = 0; i < NPG_; i++) {
        size_t n = (size_t)g*NPG_ + i;
        const float* a = na + n*3*H_;
        float nf = p0*a[h] + p1*a[H_+h] + p2*a[2*H_+h];
        acc = fmaf(dist[n], nf, acc);
    }
    QA[(size_t)g*2*H_ + h]      = Q[(size_t)g*H_ + h];
    QA[(size_t)g*2*H_ + H_ + h] = acc;
}

// ---------------- launchers ----------------
static inline void tc_gemm(const float* A, int lda, const float* Bm, int ldb,
                           float* C, int ldc, int M, int N, int K,
                           const float* bias, int splitk = 1) {
    dim3 g((N + GB_N - 1)/GB_N, (M + GB_M - 1)/GB_M, splitk);
    mma_gemm_k<false><<<g, 128, G_SMEM_BYTES>>>(A, lda, Bm, ldb, C, ldc, M, N, K,
                                                bias, splitk, nullptr, nullptr);
}
static inline void tc_gemm_expa(const float* A, int lda, const float* Bm, int ldb,
                                float* C, int ldc, int M, int N, int K,
                                int splitk, const float* rm, const float* ri) {
    dim3 g((N + GB_N - 1)/GB_N, (M + GB_M - 1)/GB_M, splitk);
    mma_gemm_k<true><<<g, 128, G_SMEM_BYTES>>>(A, lda, Bm, ldb, C, ldc, M, N, K,
                                               nullptr, splitk, rm, ri);
}

extern "C" void kernel_launch(void* const* d_in, const int* in_sizes, int n_in,
                              void* d_out, int out_size) {
    const float* questions     = (const float*)d_in[0];
    const float* node_attrs    = (const float*)d_in[1];
    const float* edge_attrs    = (const float*)d_in[2];
    const float* vocab         = (const float*)d_in[3];
    const float* default_embed = (const float*)d_in[4];
    const float* W_norm        = (const float*)d_in[5];
    const float* lstm_Wih      = (const float*)d_in[6];
    const float* lstm_Whh      = (const float*)d_in[7];
    const float* lstm_bih      = (const float*)d_in[8];
    const float* lstm_bhh      = (const float*)d_in[9];
    const float* rnn_Wih       = (const float*)d_in[10];
    const float* rnn_Whh       = (const float*)d_in[11];
    const float* rnn_bih       = (const float*)d_in[12];
    const float* rnn_bhh       = (const float*)d_in[13];
    const float* prop_embeds   = (const float*)d_in[14];
    const float* Ws_property   = (const float*)d_in[15];
    const float* W_state       = (const float*)d_in[16];
    const float* W_relation    = (const float*)d_in[17];
    const float* lin_W         = (const float*)d_in[18];
    const float* lin_b         = (const float*)d_in[19];
    const int*   lengths       = (const int*)d_in[20];
    const int*   node_graph    = (const int*)d_in[21];
    const int*   edge_graph    = (const int*)d_in[22];
    const int*   edge_src      = (const int*)d_in[23];
    const int*   edge_dst      = (const int*)d_in[24];
    float* out = (float*)d_out;

    cudaFuncSetAttribute(mma_gemm_k<false>, cudaFuncAttributeMaxDynamicSharedMemorySize, G_SMEM_BYTES);
    cudaFuncSetAttribute(mma_gemm_k<true>,  cudaFuncAttributeMaxDynamicSharedMemorySize, G_SMEM_BYTES);
    cudaFuncSetAttribute(lstm_mma_k, cudaFuncAttributeMaxDynamicSharedMemorySize, L_SMEM_BYTES);

    float* S = nullptr;
    cudaGetSymbolAddress((void**)&S, g_scratch);
    float* Cc   = S + OFF_C;
    float* XW   = S + OFF_XW;
    float* LG   = S + OFF_LOG;
    float* RM   = S + OFF_RM;
    float* RI   = S + OFF_RI;
    float* VT   = S + OFF_VT;
    float* XG   = S + OFF_XG;
    float* H0   = S + OFF_H;
    float* Cst  = S + OFF_CS;
    float* H1   = S + OFF_H2;
    float* Rr   = S + OFF_R;
    float* PS4  = S + OFF_PS;
    float* TR   = S + OFF_TR;
    float* ET   = S + OFF_ET;
    float* NS4  = S + OFF_NS4;
    float* ES4  = S + OFF_ES4;
    float* DIST = S + OFF_DIST;
    float* QA   = S + OFF_QA;
    float* WNT  = S + OFF_WNT;
    float* VOCT = S + OFF_VOCT;
    float* WIHT = S + OFF_WIHT;
    float* WHHT = S + OFF_WHHT;

    // 0. one-time layout prep
    build_c_k<<<((V_+1)*H_ + 255)/256, 256>>>(vocab, default_embed, Cc);
    transpose_wn_k<<<dim3(8,8), dim3(32,8)>>>(W_norm, WNT);
    transpose_wn_k<<<dim3(8,8), dim3(32,8)>>>(rnn_Wih, WIHT);
    transpose_wn_k<<<dim3(8,8), dim3(32,8)>>>(rnn_Whh, WHHT);
    vocab_t_k<<<dim3((LDLOG_+31)/32, H_/32), dim3(32,8)>>>(vocab, VOCT);

    // 1. vocab tagging (stats-only softmax; exp fused into Vtag GEMM A-loader)
    tc_gemm(questions, H_, WNT, H_, XW, H_, BL_, H_, H_, nullptr);
    tc_gemm(XW, H_, Cc, H_, LG, LDLOG_, BL_, V_+1, H_, nullptr);
    row_softmax_stats_k<<<BL_, 256>>>(LG, RM, RI);
    vtag_init_k<<<BL_*H_/256, 256>>>(questions, LG, RM, RI, VT);
    tc_gemm_expa(LG, LDLOG_, VOCT, LDLOG_, VT, H_, BL_, H_, V_, 4, RM, RI);

    // 2. LSTM encoder (tensor-core fused step)
    tc_gemm(VT, H_, lstm_Wih, H_, XG, 4*H_, BL_, 4*H_, H_, lstm_bih);
    zero_k<<<(2*B_*H_ + 255)/256, 256>>>(H0, 2*B_*H_);
    for (int t = 0; t < L_; t++) {
        const float* hin = (t & 1) ? H1 : H0;
        float* hout      = (t & 1) ? H0 : H1;
        lstm_mma_k<<<dim3(H_/32, B_/64), 128, L_SMEM_BYTES>>>(hin, hout, Cst, XG,
                                                              lstm_Whh, lstm_bhh, lengths, t);
    }

    // 3. fused decoder + attention
    dec_attn_k<<<B_, 256>>>(H0, WIHT, WHHT, rnn_bih, rnn_bhh, VT, lengths, Rr);

    // 4. loop-invariant graph transforms
    for (int p = 0; p < 3; p++)
        tc_gemm(node_attrs + p*H_, 3*H_, Ws_property + (size_t)p*H_*H_, H_,
                TR + p*H_, 3*H_, N_, H_, H_, nullptr);
    tc_gemm(edge_attrs, H_, Ws_property + (size_t)3*H_*H_, H_, ET, H_, E_, H_, H_, nullptr);

    // 5. reasoning
    prop_all_k<<<dim3(B_, STEPS_), 128>>>(Rr, prop_embeds, PS4);
    scores_k<<<NODE_BLKS + EDGE_BLKS, 256>>>(TR, ET, Rr, PS4, W_state, W_relation,
                                             node_graph, edge_graph, NS4, ES4);
    graph_loop_k<<<B_, 256>>>(NS4, ES4, PS4, edge_src, edge_dst, DIST);

    // 6. final aggregation + output projection
    final_agg_qa_k<<<B_, 256>>>(node_attrs, PS4, DIST, H0, QA);
    zero_k<<<(B_*OUT_ + 255)/256, 256>>>(out, B_*OUT_);
    tc_gemm(QA, 2*H_, lin_W, 2*H_, out, OUT_, B_, OUT_, 2*H_, lin_b, 4);
}

// round 14
// speedup vs baseline: 1.1092x; 1.1092x over previous
#include <cuda_runtime.h>
#include <math.h>
#include <stdint.h>

#define B_      256
#define L_      16
#define H_      256
#define V_      5000
#define P_      4
#define NPG_    150
#define DEG_    4
#define EPG_    (NPG_*DEG_)
#define STEPS_  4
#define OUT_    2000
#define N_      (B_*NPG_)
#define E_      (N_*DEG_)
#define BL_     (B_*L_)
#define LDLOG_  5008

// ---------------- scratch arena ----------------
static constexpr size_t SZ_C    = (size_t)(V_+1)*H_;
static constexpr size_t SZ_XW   = (size_t)BL_*H_;
static constexpr size_t SZ_LOG  = (size_t)BL_*LDLOG_;
static constexpr size_t SZ_VT   = (size_t)BL_*H_;
static constexpr size_t SZ_XG   = (size_t)BL_*4*H_;
static constexpr size_t SZ_H    = (size_t)B_*H_;
static constexpr size_t SZ_HINS = (size_t)B_*STEPS_*H_;
static constexpr size_t SZ_TR   = (size_t)N_*3*H_;
static constexpr size_t SZ_ET   = (size_t)E_*H_;

static constexpr size_t OFF_C    = 0;
static constexpr size_t OFF_XW   = OFF_C    + SZ_C;
static constexpr size_t OFF_LOG  = OFF_XW   + SZ_XW;
static constexpr size_t OFF_VT   = OFF_LOG  + SZ_LOG;
static constexpr size_t OFF_XG   = OFF_VT   + SZ_VT;
static constexpr size_t OFF_H    = OFF_XG   + SZ_XG;
static constexpr size_t OFF_CS   = OFF_H    + SZ_H;
static constexpr size_t OFF_H2   = OFF_CS   + SZ_H;
static constexpr size_t OFF_R    = OFF_H2   + SZ_H;
static constexpr size_t OFF_PS   = OFF_R    + SZ_HINS;
static constexpr size_t OFF_TR   = OFF_PS   + (size_t)B_*STEPS_*P_;
static constexpr size_t OFF_ET   = OFF_TR   + SZ_TR;
static constexpr size_t OFF_NS4  = OFF_ET   + SZ_ET;
static constexpr size_t OFF_ES4  = OFF_NS4  + (size_t)N_*4;
static constexpr size_t OFF_DIST = OFF_ES4  + (size_t)E_*4;
static constexpr size_t OFF_QA   = OFF_DIST + N_;
static constexpr size_t OFF_WNT  = OFF_QA   + (size_t)B_*2*H_;
static constexpr size_t OFF_VOCT = OFF_WNT  + (size_t)H_*H_;
static constexpr size_t OFF_WIHT = OFF_VOCT + (size_t)H_*LDLOG_;
static constexpr size_t OFF_WHHT = OFF_WIHT + (size_t)H_*H_;
static constexpr size_t TOTAL_SCRATCH = OFF_WHHT + (size_t)H_*H_;

__device__ __align__(16) float g_scratch[TOTAL_SCRATCH];

// ---------------- helpers ----------------
__device__ __forceinline__ float warp_sum(float v) {
    #pragma unroll
    for (int o = 16; o > 0; o >>= 1) v += __shfl_down_sync(0xffffffffu, v, o);
    return v;
}
__device__ __forceinline__ float sigmoidf_(float x) { return 1.f / (1.f + expf(-x)); }
__device__ __forceinline__ uint32_t f2tf32(float x) {
    uint32_t u;
    asm("cvt.rna.tf32.f32 %0, %1;" : "=r"(u) : "f"(x));
    return u;
}
__device__ __forceinline__ uint32_t smem_u32(const void* p) {
    uint32_t a;
    asm("{ .reg .u64 t; cvta.to.shared.u64 t, %1; cvt.u32.u64 %0, t; }" : "=r"(a) : "l"(p));
    return a;
}
__device__ __forceinline__ void cp_async16(void* sdst, const void* gsrc, bool pred) {
    uint32_t d = smem_u32(sdst);
    int sz = pred ? 16 : 0;
    asm volatile("cp.async.cg.shared.global [%0], [%1], 16, %2;"
                 :: "r"(d), "l"(gsrc), "r"(sz));
}
__device__ __forceinline__ void cp_commit() {
    asm volatile("cp.async.commit_group;" ::: "memory");
}
template<int N>
__device__ __forceinline__ void cp_wait() {
    asm volatile("cp.async.wait_group %0;" :: "n"(N) : "memory");
}
__device__ __forceinline__ void mma_tf32(float* d, const uint32_t* a, const uint32_t* b) {
    asm volatile(
        "mma.sync.aligned.m16n8k8.row.col.f32.tf32.tf32.f32 "
        "{%0,%1,%2,%3}, {%4,%5,%6,%7}, {%8,%9}, {%0,%1,%2,%3};"
        : "+f"(d[0]), "+f"(d[1]), "+f"(d[2]), "+f"(d[3])
        : "r"(a[0]), "r"(a[1]), "r"(a[2]), "r"(a[3]), "r"(b[0]), "r"(b[1]));
}

// ---------------- tf32 GEMM: CTA 128x128x32, 128 thr, warp 64x64 (2x2) ----------------
#define GB_M 128
#define GB_N 128
#define GB_K 32
#define GTS  36
#define GABUF (GB_M*GTS)
#define GBBUF (GB_N*GTS)
#define G_SMEM_BYTES ((2*GABUF + 2*GBBUF)*4)

__global__ void __launch_bounds__(128, 2)
mma_gemm_k(const float* __restrict__ A, int lda,
           const float* __restrict__ Bm, int ldb,
           float* __restrict__ C, int ldc,
           int M, int N, int K, const float* __restrict__ bias, int splitk)
{
    extern __shared__ float smf[];
    float* As = smf;
    float* Bs = smf + 2*GABUF;
    const int tid  = threadIdx.x;
    const int wid  = tid >> 5, lane = tid & 31;
    const int g    = lane >> 2, t4 = lane & 3;
    const int wm   = wid & 1, wn = wid >> 1;
    const int bm   = blockIdx.y * GB_M;
    const int bn   = blockIdx.x * GB_N;

    int kbeg = 0, kend = K;
    if (splitk > 1) {
        int kslen = (((K + splitk - 1) / splitk) + 3) & ~3;
        kbeg  = blockIdx.z * kslen;
        kend  = min(K, kbeg + kslen);
    }

    float acc[4][8][4];
    #pragma unroll
    for (int i = 0; i < 4; i++)
        #pragma unroll
        for (int j = 0; j < 8; j++)
            #pragma unroll
            for (int q = 0; q < 4; q++) acc[i][j][q] = 0.f;

    const int lrow = tid >> 3, lc4 = (tid & 7) << 2;

    auto issue_chunk = [&](int c) {
        int k0 = kbeg + c * GB_K;
        int buf = c & 1;
        #pragma unroll
        for (int i = 0; i < 8; i++) {
            int row = lrow + i*16;
            int gm = bm + row, gk = k0 + lc4;
            cp_async16(As + buf*GABUF + row*GTS + lc4,
                       A + (size_t)gm*lda + gk, (gm < M) && (gk < kend));
        }
        #pragma unroll
        for (int i = 0; i < 8; i++) {
            int row = lrow + i*16;
            int gn = bn + row, gk = k0 + lc4;
            cp_async16(Bs + buf*GBBUF + row*GTS + lc4,
                       Bm + (size_t)gn*ldb + gk, (gn < N) && (gk < kend));
        }
        cp_commit();
    };

    const int nch = (kend - kbeg + GB_K - 1) / GB_K;
    issue_chunk(0);

    for (int c = 0; c < nch; c++) {
        if (c + 1 < nch) { issue_chunk(c + 1); cp_wait<1>(); }
        else             { cp_wait<0>(); }
        __syncthreads();

        const float* Ab = As + (c & 1)*GABUF;
        const float* Bb = Bs + (c & 1)*GBBUF;
        #pragma unroll
        for (int ks = 0; ks < 4; ks++) {
            uint32_t af[4][4], bf[8][2];
            #pragma unroll
            for (int mt = 0; mt < 4; mt++) {
                int r0 = (wm*64 + mt*16 + g)*GTS + ks*8 + t4;
                af[mt][0] = f2tf32(Ab[r0]);
                af[mt][1] = f2tf32(Ab[r0 + 8*GTS]);
                af[mt][2] = f2tf32(Ab[r0 + 4]);
                af[mt][3] = f2tf32(Ab[r0 + 8*GTS + 4]);
            }
            #pragma unroll
            for (int nt = 0; nt < 8; nt++) {
                int rb = (wn*64 + nt*8 + g)*GTS + ks*8 + t4;
                bf[nt][0] = f2tf32(Bb[rb]);
                bf[nt][1] = f2tf32(Bb[rb + 4]);
            }
            #pragma unroll
            for (int mt = 0; mt < 4; mt++)
                #pragma unroll
                for (int nt = 0; nt < 8; nt++)
                    mma_tf32(acc[mt][nt], af[mt], bf[nt]);
        }
        __syncthreads();
    }

    const bool addb = (bias != nullptr) && (blockIdx.z == 0);
    #pragma unroll
    for (int mt = 0; mt < 4; mt++) {
        int row0 = bm + wm*64 + mt*16 + g;
        #pragma unroll
        for (int nt = 0; nt < 8; nt++) {
            int col0 = bn + wn*64 + nt*8 + t4*2;
            float b0v = 0.f, b1v = 0.f;
            if (addb) {
                if (col0     < N) b0v = bias[col0];
                if (col0 + 1 < N) b1v = bias[col0+1];
            }
            if (splitk > 1) {
                if (row0 < M) {
                    if (col0     < N) atomicAdd(&C[(size_t)row0*ldc + col0    ], acc[mt][nt][0] + b0v);
                    if (col0 + 1 < N) atomicAdd(&C[(size_t)row0*ldc + col0 + 1], acc[mt][nt][1] + b1v);
                }
                if (row0 + 8 < M) {
                    if (col0     < N) atomicAdd(&C[(size_t)(row0+8)*ldc + col0    ], acc[mt][nt][2] + b0v);
                    if (col0 + 1 < N) atomicAdd(&C[(size_t)(row0+8)*ldc + col0 + 1], acc[mt][nt][3] + b1v);
                }
            } else {
                if (row0 < M) {
                    if (col0     < N) C[(size_t)row0*ldc + col0    ] = acc[mt][nt][0] + b0v;
                    if (col0 + 1 < N) C[(size_t)row0*ldc + col0 + 1] = acc[mt][nt][1] + b1v;
                }
                if (row0 + 8 < M) {
                    if (col0     < N) C[(size_t)(row0+8)*ldc + col0    ] = acc[mt][nt][2] + b0v;
                    if (col0 + 1 < N) C[(size_t)(row0+8)*ldc + col0 + 1] = acc[mt][nt][3] + b1v;
                }
            }
        }
    }
}

// ---------------- tensor-core fused LSTM step ----------------
#define LB_M 64
#define LB_N 128
#define LTS  36
#define LABUF (LB_M*LTS)
#define LBBUF (LB_N*LTS)
#define L_SMEM_BYTES ((2*LABUF + 2*LBBUF)*4)

__global__ void __launch_bounds__(128, 2)
lstm_mma_k(const float* __restrict__ hin,
           float* __restrict__ hout,
           float* __restrict__ cst,
           const float* __restrict__ Xg,
           const float* __restrict__ Whh,
           const float* __restrict__ bhh,
           const int* __restrict__ lengths, int t)
{
    extern __shared__ float smf[];
    float* As = smf;
    float* Bs = smf + 2*LABUF;
    float* Cs = smf;
    const int tid = threadIdx.x;
    const int wid = tid >> 5, lane = tid & 31;
    const int g   = lane >> 2, t4 = lane & 3;
    const int wm  = wid & 1, wn = wid >> 1;
    const int hh0 = blockIdx.x * 32;
    const int bm  = blockIdx.y * LB_M;

    float acc[2][8][4];
    #pragma unroll
    for (int i = 0; i < 2; i++)
        #pragma unroll
        for (int j = 0; j < 8; j++)
            #pragma unroll
            for (int q = 0; q < 4; q++) acc[i][j][q] = 0.f;

    const int lrow = tid >> 3, lc4 = (tid & 7) << 2;

    auto issue_chunk = [&](int c) {
        int k0 = c * GB_K;
        int buf = c & 1;
        #pragma unroll
        for (int i = 0; i < 4; i++) {
            int row = lrow + i*16;
            cp_async16(As + buf*LABUF + row*LTS + lc4,
                       hin + (size_t)(bm + row)*H_ + k0 + lc4, true);
        }
        #pragma unroll
        for (int i = 0; i < 8; i++) {
            int row = lrow + i*16;
            int gn = (row >> 5)*H_ + hh0 + (row & 31);
            cp_async16(Bs + buf*LBBUF + row*LTS + lc4,
                       Whh + (size_t)gn*H_ + k0 + lc4, true);
        }
        cp_commit();
    };

    const int nch = H_ / GB_K;
    issue_chunk(0);
    for (int c = 0; c < nch; c++) {
        if (c + 1 < nch) { issue_chunk(c + 1); cp_wait<1>(); }
        else             { cp_wait<0>(); }
        __syncthreads();
        const float* Ab = As + (c & 1)*LABUF;
        const float* Bb = Bs + (c & 1)*LBBUF;
        #pragma unroll
        for (int ks = 0; ks < 4; ks++) {
            uint32_t af[2][4], bf[8][2];
            #pragma unroll
            for (int mt = 0; mt < 2; mt++) {
                int r0 = (wm*32 + mt*16 + g)*LTS + ks*8 + t4;
                af[mt][0] = f2tf32(Ab[r0]);
                af[mt][1] = f2tf32(Ab[r0 + 8*LTS]);
                af[mt][2] = f2tf32(Ab[r0 + 4]);
                af[mt][3] = f2tf32(Ab[r0 + 8*LTS + 4]);
            }
            #pragma unroll
            for (int nt = 0; nt < 8; nt++) {
                int rb = (wn*64 + nt*8 + g)*LTS + ks*8 + t4;
                bf[nt][0] = f2tf32(Bb[rb]);
                bf[nt][1] = f2tf32(Bb[rb + 4]);
            }
            #pragma unroll
            for (int mt = 0; mt < 2; mt++)
                #pragma unroll
                for (int nt = 0; nt < 8; nt++)
                    mma_tf32(acc[mt][nt], af[mt], bf[nt]);
        }
        __syncthreads();
    }

    #pragma unroll
    for (int mt = 0; mt < 2; mt++) {
        int row0 = wm*32 + mt*16 + g;
        #pragma unroll
        for (int nt = 0; nt < 8; nt++) {
            int col0 = wn*64 + nt*8 + t4*2;
            Cs[row0*132 + col0]       = acc[mt][nt][0];
            Cs[row0*132 + col0 + 1]   = acc[mt][nt][1];
            Cs[(row0+8)*132 + col0]   = acc[mt][nt][2];
            Cs[(row0+8)*132 + col0+1] = acc[mt][nt][3];
        }
    }
    __syncthreads();

    #pragma unroll
    for (int i = 0; i < 16; i++) {
        int cell = i*128 + tid;
        int b_l = cell >> 5, hh_l = cell & 31;
        int b = bm + b_l, hh = hh0 + hh_l;
        const float* xrow = Xg + (size_t)(b*L_ + t)*(4*H_);
        float gi = Cs[b_l*132 + 0*32 + hh_l] + xrow[hh]        + bhh[hh];
        float gf = Cs[b_l*132 + 1*32 + hh_l] + xrow[H_+hh]     + bhh[H_+hh];
        float gc = Cs[b_l*132 + 2*32 + hh_l] + xrow[2*H_+hh]   + bhh[2*H_+hh];
        float go = Cs[b_l*132 + 3*32 + hh_l] + xrow[3*H_+hh]   + bhh[3*H_+hh];
        size_t idx = (size_t)b*H_ + hh;
        if (t < lengths[b]) {
            float cn = sigmoidf_(gf)*cst[idx] + sigmoidf_(gi)*tanhf(gc);
            cst[idx] = cn;
            hout[idx] = sigmoidf_(go)*tanhf(cn);
        } else {
            hout[idx] = hin[idx];
        }
    }
}

// ---------------- fused decoder RNN + attention ----------------
__global__ void __launch_bounds__(256)
dec_attn_k(const float* __restrict__ Q,
           const float* __restrict__ WihT,
           const float* __restrict__ WhhT,
           const float* __restrict__ bih, const float* __restrict__ bhh,
           const float* __restrict__ Vt,
           const int* __restrict__ lengths,
           float* __restrict__ R)
{
    int b = blockIdx.x, tid = threadIdx.x;
    __shared__ float shh[H_], sQ[H_], sh[H_];
    __shared__ float sV[L_][H_];
    __shared__ float sHins[STEPS_][H_];
    __shared__ float satt[STEPS_][L_];

    shh[tid] = Q[(size_t)b*H_ + tid];
    for (int i = tid; i < L_*H_; i += 256) sV[i>>8][i&255] = Vt[(size_t)b*L_*H_ + i];
    __syncthreads();

    float acc = bih[tid];
    #pragma unroll 8
    for (int k = 0; k < H_; k++) acc = fmaf(shh[k], WihT[(size_t)k*H_ + tid], acc);
    sQ[tid] = acc;
    sh[tid] = 0.f;
    __syncthreads();

    for (int s = 0; s < STEPS_; s++) {
        float v = sQ[tid] + bhh[tid];
        #pragma unroll 8
        for (int k = 0; k < H_; k++) v = fmaf(sh[k], WhhT[(size_t)k*H_ + tid], v);
        v = fmaxf(v, 0.f);
        __syncthreads();
        sh[tid] = v;
        sHins[s][tid] = v;
        __syncthreads();
    }

    int warp = tid >> 5, lane = tid & 31;
    for (int pid = warp; pid < STEPS_*L_; pid += 8) {
        int s = pid >> 4, l = pid & 15;
        float a = 0.f;
        #pragma unroll
        for (int q = 0; q < H_/32; q++) a = fmaf(sHins[s][lane+32*q], sV[l][lane+32*q], a);
        a = warp_sum(a);
        if (lane == 0) satt[s][l] = a;
    }
    __syncthreads();
    if (tid < STEPS_) {
        int len = lengths[b];
        float m = -3.4e38f;
        for (int l = 0; l < len; l++) m = fmaxf(m, satt[tid][l]);
        float s = 0.f;
        for (int l = 0; l < len; l++) { float e = expf(satt[tid][l]-m); satt[tid][l]=e; s+=e; }
        float inv = 1.f/s;
        for (int l = 0; l < L_; l++) satt[tid][l] = (l < len) ? satt[tid][l]*inv : 0.f;
    }
    __syncthreads();
    for (int s = 0; s < STEPS_; s++) {
        float a2 = 0.f;
        #pragma unroll
        for (int l = 0; l < L_; l++) a2 = fmaf(satt[s][l], sV[l][tid], a2);
        R[((size_t)b*STEPS_ + s)*H_ + tid] = a2;
    }
}

// ---------------- small kernels ----------------
__global__ void build_c_k(const float* __restrict__ vocab, const float* __restrict__ de,
                          float* __restrict__ Cc) {
    int i = blockIdx.x*256 + threadIdx.x;
    if (i < (V_+1)*H_) Cc[i] = (i < V_*H_) ? vocab[i] : de[i - (size_t)V_*H_];
}

__global__ void transpose_wn_k(const float* __restrict__ W, float* __restrict__ WT) {
    __shared__ float t[32][33];
    int rb = blockIdx.y*32, cb = blockIdx.x*32;
    int x = threadIdx.x, y = threadIdx.y;
    for (int j = y; j < 32; j += 8) t[j][x] = W[(size_t)(rb+j)*H_ + cb + x];
    __syncthreads();
    for (int j = y; j < 32; j += 8) WT[(size_t)(cb+j)*H_ + rb + x] = t[x][j];
}

__global__ void vocab_t_k(const float* __restrict__ vocab, float* __restrict__ vt) {
    __shared__ float t[32][33];
    int vb = blockIdx.x*32, hb = blockIdx.y*32;
    int x = threadIdx.x, y = threadIdx.y;
    for (int j = y; j < 32; j += 8) {
        int v = vb + j;
        t[j][x] = (v < V_) ? vocab[(size_t)v*H_ + hb + x] : 0.f;
    }
    __syncthreads();
    for (int j = y; j < 32; j += 8) {
        int v = vb + x;
        if (v < LDLOG_) vt[(size_t)(hb+j)*LDLOG_ + v] = t[x][j];
    }
}

__global__ void zero_k(float* __restrict__ p, int n) {
    int i = blockIdx.x*256 + threadIdx.x;
    if (i < n) p[i] = 0.f;
}

// 3-pass softmax, single exp pass: p1 max, p2 write exp(x-M)+sum, p3 scale.
__global__ void row_softmax_w_k(float* __restrict__ Lg) {
    int r = blockIdx.x;
    float* row = Lg + (size_t)r*LDLOG_;
    __shared__ float red[256];
    float m = -3.4e38f;
    for (int j = threadIdx.x; j < V_+1; j += 256) m = fmaxf(m, row[j]);
    red[threadIdx.x] = m; __syncthreads();
    for (int o = 128; o > 0; o >>= 1) {
        if (threadIdx.x < o) red[threadIdx.x] = fmaxf(red[threadIdx.x], red[threadIdx.x+o]);
        __syncthreads();
    }
    float M = red[0]; __syncthreads();
    float s = 0.f;
    for (int j = threadIdx.x; j < V_+1; j += 256) {
        float e = expf(row[j] - M);
        row[j] = e;
        s += e;
    }
    red[threadIdx.x] = s; __syncthreads();
    for (int o = 128; o > 0; o >>= 1) {
        if (threadIdx.x < o) red[threadIdx.x] += red[threadIdx.x+o];
        __syncthreads();
    }
    float inv = 1.f/red[0];
    for (int j = threadIdx.x; j < V_+1; j += 256)
        row[j] *= inv;
}

// VT init: epsilon term w*words (split-K Vtag GEMM accumulates on top)
__global__ void vtag_init_k(const float* __restrict__ words, const float* __restrict__ Lg,
                            float* __restrict__ Vt) {
    int i = blockIdx.x*256 + threadIdx.x;
    int r = i >> 8;
    float w = Lg[(size_t)r*LDLOG_ + V_];
    Vt[i] = w * words[i];
}

__global__ void __launch_bounds__(128)
prop_all_k(const float* __restrict__ R, const float* __restrict__ pe,
           float* __restrict__ ps4) {
    int b = blockIdx.x, s = blockIdx.y;
    int p = threadIdx.x >> 5, lane = threadIdx.x & 31;
    const float* instr = R + ((size_t)b*STEPS_ + s)*H_;
    float acc = 0.f;
    for (int h = lane; h < H_; h += 32) acc = fmaf(instr[h], pe[p*H_ + h], acc);
    acc = warp_sum(acc);
    __shared__ float s4[P_];
    if (lane == 0) s4[p] = acc;
    __syncthreads();
    if (threadIdx.x == 0) {
        float m = fmaxf(fmaxf(s4[0], s4[1]), fmaxf(s4[2], s4[3]));
        float e0 = expf(s4[0]-m), e1 = expf(s4[1]-m), e2 = expf(s4[2]-m), e3 = expf(s4[3]-m);
        float inv = 1.f/(e0+e1+e2+e3);
        float* o = ps4 + ((size_t)b*STEPS_ + s)*P_;
        o[0]=e0*inv; o[1]=e1*inv; o[2]=e2*inv; o[3]=e3*inv;
    }
}

#define NODE_BLKS (N_/8)
#define EDGE_BLKS (E_/8)
__global__ void __launch_bounds__(256)
scores_k(const float* __restrict__ Tr, const float* __restrict__ Et,
         const float* __restrict__ R, const float* __restrict__ ps4,
         const float* __restrict__ Wst, const float* __restrict__ Wrel,
         const int* __restrict__ ng, const int* __restrict__ eg,
         float* __restrict__ ns4, float* __restrict__ es4) {
    int bid = blockIdx.x;
    int warp = threadIdx.x >> 5, lane = threadIdx.x & 31;
    if (bid < NODE_BLKS) {
        int n = bid*8 + warp;
        int g = ng[n];
        const float* T = Tr + (size_t)n*3*H_;
        float t0[8], t1[8], t2[8], ws[8];
        #pragma unroll
        for (int q = 0; q < 8; q++) {
            int h = lane + 32*q;
            t0[q] = T[h]; t1[q] = T[H_+h]; t2[q] = T[2*H_+h]; ws[q] = Wst[h];
        }
        float out[STEPS_];
        #pragma unroll
        for (int s = 0; s < STEPS_; s++) {
            const float* pp = ps4 + ((size_t)g*STEPS_ + s)*P_;
            float p0 = pp[0], p1 = pp[1], p2 = pp[2];
            const float* instr = R + ((size_t)g*STEPS_ + s)*H_;
            float acc = 0.f;
            #pragma unroll
            for (int q = 0; q < 8; q++) {
                int h = lane + 32*q;
                float tv = p0*t0[q] + p1*t1[q] + p2*t2[q];
                float x = instr[h]*tv;
                float e = (x > 0.f) ? x : expm1f(x);
                acc = fmaf(e, ws[q], acc);
            }
            out[s] = warp_sum(acc);
        }
        if (lane == 0)
            *reinterpret_cast<float4*>(ns4 + (size_t)n*4) =
                make_float4(out[0], out[1], out[2], out[3]);
    } else {
        int e = (bid - NODE_BLKS)*8 + warp;
        int g = eg[e];
        const float* et = Et + (size_t)e*H_;
        float ev[8], wr[8];
        #pragma unroll
        for (int q = 0; q < 8; q++) {
            int h = lane + 32*q;
            ev[q] = et[h]; wr[q] = Wrel[h];
        }
        float out[STEPS_];
        #pragma unroll
        for (int s = 0; s < STEPS_; s++) {
            const float* instr = R + ((size_t)g*STEPS_ + s)*H_;
            float acc = 0.f;
            #pragma unroll
            for (int q = 0; q < 8; q++) {
                int h = lane + 32*q;
                float x = instr[h]*ev[q];
                float el = (x > 0.f) ? x : expm1f(x);
                acc = fmaf(el, wr[q], acc);
            }
            out[s] = warp_sum(acc);
        }
        if (lane == 0)
            *reinterpret_cast<float4*>(es4 + (size_t)e*4) =
                make_float4(out[0], out[1], out[2], out[3]);
    }
}

__global__ void __launch_bounds__(256)
graph_loop_k(const float* __restrict__ ns4, const float* __restrict__ es4,
             const float* __restrict__ ps4,
             const int* __restrict__ esrc, const int* __restrict__ edst,
             float* __restrict__ dist_out) {
    int g = blockIdx.x, tid = threadIdx.x;
    __shared__ float dist[NPG_], agg[NPG_], red[256];
    __shared__ int lsrc[EPG_], ldst[EPG_];
    __shared__ float4 ns[NPG_];

    int nbase = g*NPG_, ebase = g*EPG_;
    for (int e = tid; e < EPG_; e += 256) {
        lsrc[e] = esrc[ebase + e] - nbase;
        ldst[e] = edst[ebase + e] - nbase;
    }
    if (tid < NPG_) {
        dist[tid] = 1.f/(float)NPG_;
        ns[tid] = *reinterpret_cast<const float4*>(ns4 + (size_t)(nbase + tid)*4);
    }
    __syncthreads();

    for (int s = 0; s < STEPS_; s++) {
        if (tid < NPG_) agg[tid] = 0.f;
        __syncthreads();
        for (int e = tid; e < EPG_; e += 256) {
            float sc = es4[(size_t)(ebase + e)*4 + s];
            atomicAdd(&agg[ldst[e]], dist[lsrc[e]]*sc);
        }
        __syncthreads();

        float nsv = (tid < NPG_) ? ((const float*)&ns[tid])[s] : -3.4e38f;
        float agv = (tid < NPG_) ? agg[tid] : -3.4e38f;
        red[tid] = nsv; __syncthreads();
        for (int o = 128; o > 0; o >>= 1) { if (tid < o) red[tid] = fmaxf(red[tid], red[tid+o]); __syncthreads(); }
        float m1 = red[0]; __syncthreads();
        red[tid] = agv; __syncthreads();
        for (int o = 128; o > 0; o >>= 1) { if (tid < o) red[tid] = fmaxf(red[tid], red[tid+o]); __syncthreads(); }
        float m2 = red[0]; __syncthreads();
        float e1 = (tid < NPG_) ? expf(nsv - m1) : 0.f;
        float e2 = (tid < NPG_) ? expf(agv - m2) : 0.f;
        red[tid] = e1; __syncthreads();
        for (int o = 128; o > 0; o >>= 1) { if (tid < o) red[tid] += red[tid+o]; __syncthreads(); }
        float s1 = red[0]; __syncthreads();
        red[tid] = e2; __syncthreads();
        for (int o = 128; o > 0; o >>= 1) { if (tid < o) red[tid] += red[tid+o]; __syncthreads(); }
        float s2 = red[0]; __syncthreads();
        if (tid < NPG_) {
            float r = ps4[((size_t)g*STEPS_ + s)*P_ + 3];
            dist[tid] = r*(e2/s2) + (1.f - r)*(e1/s1);
        }
        __syncthreads();
    }
    if (tid < NPG_) dist_out[nbase + tid] = dist[tid];
}

__global__ void final_agg_qa_k(const float* __restrict__ na, const float* __restrict__ ps4,
                               const float* __restrict__ dist, const float* __restrict__ Q,
                               float* __restrict__ QA) {
    int g = blockIdx.x, h = threadIdx.x;
    const float* pp = ps4 + ((size_t)g*STEPS_ + (STEPS_-1))*P_;
    float p0 = pp[0], p1 = pp[1], p2 = pp[2];
    float acc = 0.f;
    for (int i = 0; i < NPG_; i++) {
        size_t n = (size_t)g*NPG_ + i;
        const float* a = na + n*3*H_;
        float nf = p0*a[h] + p1*a[H_+h] + p2*a[2*H_+h];
        acc = fmaf(dist[n], nf, acc);
    }
    QA[(size_t)g*2*H_ + h]      = Q[(size_t)g*H_ + h];
    QA[(size_t)g*2*H_ + H_ + h] = acc;
}

// ---------------- launchers ----------------
static inline void tc_gemm(const float* A, int lda, const float* Bm, int ldb,
                           float* C, int ldc, int M, int N, int K,
                           const float* bias, int splitk = 1) {
    dim3 g((N + GB_N - 1)/GB_N, (M + GB_M - 1)/GB_M, splitk);
    mma_gemm_k<<<g, 128, G_SMEM_BYTES>>>(A, lda, Bm, ldb, C, ldc, M, N, K, bias, splitk);
}

extern "C" void kernel_launch(void* const* d_in, const int* in_sizes, int n_in,
                              void* d_out, int out_size) {
    const float* questions     = (const float*)d_in[0];
    const float* node_attrs    = (const float*)d_in[1];
    const float* edge_attrs    = (const float*)d_in[2];
    const float* vocab         = (const float*)d_in[3];
    const float* default_embed = (const float*)d_in[4];
    const float* W_norm        = (const float*)d_in[5];
    const float* lstm_Wih      = (const float*)d_in[6];
    const float* lstm_Whh      = (const float*)d_in[7];
    const float* lstm_bih      = (const float*)d_in[8];
    const float* lstm_bhh      = (const float*)d_in[9];
    const float* rnn_Wih       = (const float*)d_in[10];
    const float* rnn_Whh       = (const float*)d_in[11];
    const float* rnn_bih       = (const float*)d_in[12];
    const float* rnn_bhh       = (const float*)d_in[13];
    const float* prop_embeds   = (const float*)d_in[14];
    const float* Ws_property   = (const float*)d_in[15];
    const float* W_state       = (const float*)d_in[16];
    const float* W_relation    = (const float*)d_in[17];
    const float* lin_W         = (const float*)d_in[18];
    const float* lin_b         = (const float*)d_in[19];
    const int*   lengths       = (const int*)d_in[20];
    const int*   node_graph    = (const int*)d_in[21];
    const int*   edge_graph    = (const int*)d_in[22];
    const int*   edge_src      = (const int*)d_in[23];
    const int*   edge_dst      = (const int*)d_in[24];
    float* out = (float*)d_out;

    cudaFuncSetAttribute(mma_gemm_k, cudaFuncAttributeMaxDynamicSharedMemorySize, G_SMEM_BYTES);
    cudaFuncSetAttribute(lstm_mma_k, cudaFuncAttributeMaxDynamicSharedMemorySize, L_SMEM_BYTES);

    float* S = nullptr;
    cudaGetSymbolAddress((void**)&S, g_scratch);
    float* Cc   = S + OFF_C;
    float* XW   = S + OFF_XW;
    float* LG   = S + OFF_LOG;
    float* VT   = S + OFF_VT;
    float* XG   = S + OFF_XG;
    float* H0   = S + OFF_H;
    float* Cst  = S + OFF_CS;
    float* H1   = S + OFF_H2;
    float* Rr   = S + OFF_R;
    float* PS4  = S + OFF_PS;
    float* TR   = S + OFF_TR;
    float* ET   = S + OFF_ET;
    float* NS4  = S + OFF_NS4;
    float* ES4  = S + OFF_ES4;
    float* DIST = S + OFF_DIST;
    float* QA   = S + OFF_QA;
    float* WNT  = S + OFF_WNT;
    float* VOCT = S + OFF_VOCT;
    float* WIHT = S + OFF_WIHT;
    float* WHHT = S + OFF_WHHT;

    // 0. one-time layout prep
    build_c_k<<<((V_+1)*H_ + 255)/256, 256>>>(vocab, default_embed, Cc);
    transpose_wn_k<<<dim3(8,8), dim3(32,8)>>>(W_norm, WNT);
    transpose_wn_k<<<dim3(8,8), dim3(32,8)>>>(rnn_Wih, WIHT);
    transpose_wn_k<<<dim3(8,8), dim3(32,8)>>>(rnn_Whh, WHHT);
    vocab_t_k<<<dim3((LDLOG_+31)/32, H_/32), dim3(32,8)>>>(vocab, VOCT);

    // 1. vocab tagging (R12 structure: probs materialized, cp.async GEMM)
    tc_gemm(questions, H_, WNT, H_, XW, H_, BL_, H_, H_, nullptr);
    tc_gemm(XW, H_, Cc, H_, LG, LDLOG_, BL_, V_+1, H_, nullptr);
    row_softmax_w_k<<<BL_, 256>>>(LG);
    vtag_init_k<<<BL_*H_/256, 256>>>(questions, LG, VT);   // VT = eps term (replaces zero+post-add)
    tc_gemm(LG, LDLOG_, VOCT, LDLOG_, VT, H_, BL_, H_, V_, nullptr, 4);

    // 2. LSTM encoder (tensor-core fused step)
    tc_gemm(VT, H_, lstm_Wih, H_, XG, 4*H_, BL_, 4*H_, H_, lstm_bih);
    zero_k<<<(2*B_*H_ + 255)/256, 256>>>(H0, 2*B_*H_);
    for (int t = 0; t < L_; t++) {
        const float* hin = (t & 1) ? H1 : H0;
        float* hout      = (t & 1) ? H0 : H1;
        lstm_mma_k<<<dim3(H_/32, B_/64), 128, L_SMEM_BYTES>>>(hin, hout, Cst, XG,
                                                              lstm_Whh, lstm_bhh, lengths, t);
    }

    // 3. fused decoder + attention
    dec_attn_k<<<B_, 256>>>(H0, WIHT, WHHT, rnn_bih, rnn_bhh, VT, lengths, Rr);

    // 4. loop-invariant graph transforms
    for (int p = 0; p < 3; p++)
        tc_gemm(node_attrs + p*H_, 3*H_, Ws_property + (size_t)p*H_*H_, H_,
                TR + p*H_, 3*H_, N_, H_, H_, nullptr);
    tc_gemm(edge_attrs, H_, Ws_property + (size_t)3*H_*H_, H_, ET, H_, E_, H_, H_, nullptr);

    // 5. reasoning
    prop_all_k<<<dim3(B_, STEPS_), 128>>>(Rr, prop_embeds, PS4);
    scores_k<<<NODE_BLKS + EDGE_BLKS, 256>>>(TR, ET, Rr, PS4, W_state, W_relation,
                                             node_graph, edge_graph, NS4, ES4);
    graph_loop_k<<<B_, 256>>>(NS4, ES4, PS4, edge_src, edge_dst, DIST);

    // 6. final aggregation + output projection
    final_agg_qa_k<<<B_, 256>>>(node_attrs, PS4, DIST, H0, QA);
    zero_k<<<(B_*OUT_ + 255)/256, 256>>>(out, B_*OUT_);
    tc_gemm(QA, 2*H_, lin_W, 2*H_, out, OUT_, B_, OUT_, 2*H_, lin_b, 4);
}

// round 15
// speedup vs baseline: 1.1282x; 1.0171x over previous
#include <cuda_runtime.h>
#include <math.h>
#include <stdint.h>

#define B_      256
#define L_      16
#define H_      256
#define V_      5000
#define P_      4
#define NPG_    150
#define DEG_    4
#define EPG_    (NPG_*DEG_)
#define STEPS_  4
#define OUT_    2000
#define N_      (B_*NPG_)
#define E_      (N_*DEG_)
#define BL_     (B_*L_)
#define LDLOG_  5008

// ---------------- scratch arena ----------------
static constexpr size_t SZ_C    = (size_t)(V_+1)*H_;
static constexpr size_t SZ_XW   = (size_t)BL_*H_;
static constexpr size_t SZ_LOG  = (size_t)BL_*LDLOG_;
static constexpr size_t SZ_VT   = (size_t)BL_*H_;
static constexpr size_t SZ_XG   = (size_t)BL_*4*H_;
static constexpr size_t SZ_H    = (size_t)B_*H_;
static constexpr size_t SZ_HINS = (size_t)B_*STEPS_*H_;
static constexpr size_t SZ_TR   = (size_t)N_*3*H_;
static constexpr size_t SZ_ET   = (size_t)E_*H_;

static constexpr size_t OFF_C    = 0;
static constexpr size_t OFF_XW   = OFF_C    + SZ_C;
static constexpr size_t OFF_LOG  = OFF_XW   + SZ_XW;
static constexpr size_t OFF_VT   = OFF_LOG  + SZ_LOG;
static constexpr size_t OFF_XG   = OFF_VT   + SZ_VT;
static constexpr size_t OFF_H    = OFF_XG   + SZ_XG;
static constexpr size_t OFF_CS   = OFF_H    + SZ_H;
static constexpr size_t OFF_H2   = OFF_CS   + SZ_H;
static constexpr size_t OFF_R    = OFF_H2   + SZ_H;
static constexpr size_t OFF_PS   = OFF_R    + SZ_HINS;
static constexpr size_t OFF_TR   = OFF_PS   + (size_t)B_*STEPS_*P_;
static constexpr size_t OFF_ET   = OFF_TR   + SZ_TR;
static constexpr size_t OFF_NS4  = OFF_ET   + SZ_ET;
static constexpr size_t OFF_ES4  = OFF_NS4  + (size_t)N_*4;
static constexpr size_t OFF_DIST = OFF_ES4  + (size_t)E_*4;
static constexpr size_t OFF_QA   = OFF_DIST + N_;
static constexpr size_t OFF_WNT  = OFF_QA   + (size_t)B_*2*H_;
static constexpr size_t OFF_VOCT = OFF_WNT  + (size_t)H_*H_;
static constexpr size_t OFF_WIHT = OFF_VOCT + (size_t)H_*LDLOG_;
static constexpr size_t OFF_WHHT = OFF_WIHT + (size_t)H_*H_;
static constexpr size_t TOTAL_SCRATCH = OFF_WHHT + (size_t)H_*H_;

__device__ __align__(16) float g_scratch[TOTAL_SCRATCH];

// ---------------- helpers ----------------
__device__ __forceinline__ float warp_sum(float v) {
    #pragma unroll
    for (int o = 16; o > 0; o >>= 1) v += __shfl_down_sync(0xffffffffu, v, o);
    return v;
}
__device__ __forceinline__ float sigmoidf_(float x) { return 1.f / (1.f + expf(-x)); }
__device__ __forceinline__ uint32_t f2tf32(float x) {
    uint32_t u;
    asm("cvt.rna.tf32.f32 %0, %1;" : "=r"(u) : "f"(x));
    return u;
}
__device__ __forceinline__ uint32_t smem_u32(const void* p) {
    uint32_t a;
    asm("{ .reg .u64 t; cvta.to.shared.u64 t, %1; cvt.u32.u64 %0, t; }" : "=r"(a) : "l"(p));
    return a;
}
__device__ __forceinline__ void cp_async16(void* sdst, const void* gsrc, bool pred) {
    uint32_t d = smem_u32(sdst);
    int sz = pred ? 16 : 0;
    asm volatile("cp.async.cg.shared.global [%0], [%1], 16, %2;"
                 :: "r"(d), "l"(gsrc), "r"(sz));
}
__device__ __forceinline__ void cp_commit() {
    asm volatile("cp.async.commit_group;" ::: "memory");
}
template<int N>
__device__ __forceinline__ void cp_wait() {
    asm volatile("cp.async.wait_group %0;" :: "n"(N) : "memory");
}
__device__ __forceinline__ void mma_tf32(float* d, const uint32_t* a, const uint32_t* b) {
    asm volatile(
        "mma.sync.aligned.m16n8k8.row.col.f32.tf32.tf32.f32 "
        "{%0,%1,%2,%3}, {%4,%5,%6,%7}, {%8,%9}, {%0,%1,%2,%3};"
        : "+f"(d[0]), "+f"(d[1]), "+f"(d[2]), "+f"(d[3])
        : "r"(a[0]), "r"(a[1]), "r"(a[2]), "r"(a[3]), "r"(b[0]), "r"(b[1]));
}

// ---------------- tf32 GEMM: CTA 128x128x32, 128 thr, warp 64x64 (2x2) ----------------
#define GB_M 128
#define GB_N 128
#define GB_K 32
#define GTS  36
#define GABUF (GB_M*GTS)
#define GBBUF (GB_N*GTS)
#define G_SMEM_BYTES ((2*GABUF + 2*GBBUF)*4)

__global__ void __launch_bounds__(128, 2)
mma_gemm_k(const float* __restrict__ A, int lda,
           const float* __restrict__ Bm, int ldb,
           float* __restrict__ C, int ldc,
           int M, int N, int K, const float* __restrict__ bias, int splitk)
{
    extern __shared__ float smf[];
    float* As = smf;
    float* Bs = smf + 2*GABUF;
    const int tid  = threadIdx.x;
    const int wid  = tid >> 5, lane = tid & 31;
    const int g    = lane >> 2, t4 = lane & 3;
    const int wm   = wid & 1, wn = wid >> 1;
    const int bm   = blockIdx.y * GB_M;
    const int bn   = blockIdx.x * GB_N;

    int kbeg = 0, kend = K;
    if (splitk > 1) {
        int kslen = (((K + splitk - 1) / splitk) + 3) & ~3;
        kbeg  = blockIdx.z * kslen;
        kend  = min(K, kbeg + kslen);
    }

    float acc[4][8][4];
    #pragma unroll
    for (int i = 0; i < 4; i++)
        #pragma unroll
        for (int j = 0; j < 8; j++)
            #pragma unroll
            for (int q = 0; q < 4; q++) acc[i][j][q] = 0.f;

    const int lrow = tid >> 3, lc4 = (tid & 7) << 2;

    auto issue_chunk = [&](int c) {
        int k0 = kbeg + c * GB_K;
        int buf = c & 1;
        #pragma unroll
        for (int i = 0; i < 8; i++) {
            int row = lrow + i*16;
            int gm = bm + row, gk = k0 + lc4;
            cp_async16(As + buf*GABUF + row*GTS + lc4,
                       A + (size_t)gm*lda + gk, (gm < M) && (gk < kend));
        }
        #pragma unroll
        for (int i = 0; i < 8; i++) {
            int row = lrow + i*16;
            int gn = bn + row, gk = k0 + lc4;
            cp_async16(Bs + buf*GBBUF + row*GTS + lc4,
                       Bm + (size_t)gn*ldb + gk, (gn < N) && (gk < kend));
        }
        cp_commit();
    };

    const int nch = (kend - kbeg + GB_K - 1) / GB_K;
    issue_chunk(0);

    for (int c = 0; c < nch; c++) {
        if (c + 1 < nch) { issue_chunk(c + 1); cp_wait<1>(); }
        else             { cp_wait<0>(); }
        __syncthreads();

        const float* Ab = As + (c & 1)*GABUF;
        const float* Bb = Bs + (c & 1)*GBBUF;
        #pragma unroll
        for (int ks = 0; ks < 4; ks++) {
            uint32_t af[4][4], bf[8][2];
            #pragma unroll
            for (int mt = 0; mt < 4; mt++) {
                int r0 = (wm*64 + mt*16 + g)*GTS + ks*8 + t4;
                af[mt][0] = f2tf32(Ab[r0]);
                af[mt][1] = f2tf32(Ab[r0 + 8*GTS]);
                af[mt][2] = f2tf32(Ab[r0 + 4]);
                af[mt][3] = f2tf32(Ab[r0 + 8*GTS + 4]);
            }
            #pragma unroll
            for (int nt = 0; nt < 8; nt++) {
                int rb = (wn*64 + nt*8 + g)*GTS + ks*8 + t4;
                bf[nt][0] = f2tf32(Bb[rb]);
                bf[nt][1] = f2tf32(Bb[rb + 4]);
            }
            #pragma unroll
            for (int mt = 0; mt < 4; mt++)
                #pragma unroll
                for (int nt = 0; nt < 8; nt++)
                    mma_tf32(acc[mt][nt], af[mt], bf[nt]);
        }
        __syncthreads();
    }

    const bool addb = (bias != nullptr) && (blockIdx.z == 0);
    #pragma unroll
    for (int mt = 0; mt < 4; mt++) {
        int row0 = bm + wm*64 + mt*16 + g;
        #pragma unroll
        for (int nt = 0; nt < 8; nt++) {
            int col0 = bn + wn*64 + nt*8 + t4*2;
            float b0v = 0.f, b1v = 0.f;
            if (addb) {
                if (col0     < N) b0v = bias[col0];
                if (col0 + 1 < N) b1v = bias[col0+1];
            }
            if (splitk > 1) {
                if (row0 < M) {
                    if (col0     < N) atomicAdd(&C[(size_t)row0*ldc + col0    ], acc[mt][nt][0] + b0v);
                    if (col0 + 1 < N) atomicAdd(&C[(size_t)row0*ldc + col0 + 1], acc[mt][nt][1] + b1v);
                }
                if (row0 + 8 < M) {
                    if (col0     < N) atomicAdd(&C[(size_t)(row0+8)*ldc + col0    ], acc[mt][nt][2] + b0v);
                    if (col0 + 1 < N) atomicAdd(&C[(size_t)(row0+8)*ldc + col0 + 1], acc[mt][nt][3] + b1v);
                }
            } else {
                if (row0 < M) {
                    if (col0     < N) C[(size_t)row0*ldc + col0    ] = acc[mt][nt][0] + b0v;
                    if (col0 + 1 < N) C[(size_t)row0*ldc + col0 + 1] = acc[mt][nt][1] + b1v;
                }
                if (row0 + 8 < M) {
                    if (col0     < N) C[(size_t)(row0+8)*ldc + col0    ] = acc[mt][nt][2] + b0v;
                    if (col0 + 1 < N) C[(size_t)(row0+8)*ldc + col0 + 1] = acc[mt][nt][3] + b1v;
                }
            }
        }
    }
}

// ---------------- tensor-core fused LSTM step ----------------
#define LB_M 64
#define LB_N 128
#define LTS  36
#define LABUF (LB_M*LTS)
#define LBBUF (LB_N*LTS)
#define L_SMEM_BYTES ((2*LABUF + 2*LBBUF)*4)

__global__ void __launch_bounds__(128, 2)
lstm_mma_k(const float* __restrict__ hin,
           float* __restrict__ hout,
           float* __restrict__ cst,
           const float* __restrict__ Xg,
           const float* __restrict__ Whh,
           const float* __restrict__ bhh,
           const int* __restrict__ lengths, int t)
{
    extern __shared__ float smf[];
    float* As = smf;
    float* Bs = smf + 2*LABUF;
    float* Cs = smf;
    const int tid = threadIdx.x;
    const int wid = tid >> 5, lane = tid & 31;
    const int g   = lane >> 2, t4 = lane & 3;
    const int wm  = wid & 1, wn = wid >> 1;
    const int hh0 = blockIdx.x * 32;
    const int bm  = blockIdx.y * LB_M;

    float acc[2][8][4];
    #pragma unroll
    for (int i = 0; i < 2; i++)
        #pragma unroll
        for (int j = 0; j < 8; j++)
            #pragma unroll
            for (int q = 0; q < 4; q++) acc[i][j][q] = 0.f;

    const int lrow = tid >> 3, lc4 = (tid & 7) << 2;

    auto issue_chunk = [&](int c) {
        int k0 = c * GB_K;
        int buf = c & 1;
        #pragma unroll
        for (int i = 0; i < 4; i++) {
            int row = lrow + i*16;
            cp_async16(As + buf*LABUF + row*LTS + lc4,
                       hin + (size_t)(bm + row)*H_ + k0 + lc4, true);
        }
        #pragma unroll
        for (int i = 0; i < 8; i++) {
            int row = lrow + i*16;
            int gn = (row >> 5)*H_ + hh0 + (row & 31);
            cp_async16(Bs + buf*LBBUF + row*LTS + lc4,
                       Whh + (size_t)gn*H_ + k0 + lc4, true);
        }
        cp_commit();
    };

    const int nch = H_ / GB_K;
    issue_chunk(0);
    for (int c = 0; c < nch; c++) {
        if (c + 1 < nch) { issue_chunk(c + 1); cp_wait<1>(); }
        else             { cp_wait<0>(); }
        __syncthreads();
        const float* Ab = As + (c & 1)*LABUF;
        const float* Bb = Bs + (c & 1)*LBBUF;
        #pragma unroll
        for (int ks = 0; ks < 4; ks++) {
            uint32_t af[2][4], bf[8][2];
            #pragma unroll
            for (int mt = 0; mt < 2; mt++) {
                int r0 = (wm*32 + mt*16 + g)*LTS + ks*8 + t4;
                af[mt][0] = f2tf32(Ab[r0]);
                af[mt][1] = f2tf32(Ab[r0 + 8*LTS]);
                af[mt][2] = f2tf32(Ab[r0 + 4]);
                af[mt][3] = f2tf32(Ab[r0 + 8*LTS + 4]);
            }
            #pragma unroll
            for (int nt = 0; nt < 8; nt++) {
                int rb = (wn*64 + nt*8 + g)*LTS + ks*8 + t4;
                bf[nt][0] = f2tf32(Bb[rb]);
                bf[nt][1] = f2tf32(Bb[rb + 4]);
            }
            #pragma unroll
            for (int mt = 0; mt < 2; mt++)
                #pragma unroll
                for (int nt = 0; nt < 8; nt++)
                    mma_tf32(acc[mt][nt], af[mt], bf[nt]);
        }
        __syncthreads();
    }

    #pragma unroll
    for (int mt = 0; mt < 2; mt++) {
        int row0 = wm*32 + mt*16 + g;
        #pragma unroll
        for (int nt = 0; nt < 8; nt++) {
            int col0 = wn*64 + nt*8 + t4*2;
            Cs[row0*132 + col0]       = acc[mt][nt][0];
            Cs[row0*132 + col0 + 1]   = acc[mt][nt][1];
            Cs[(row0+8)*132 + col0]   = acc[mt][nt][2];
            Cs[(row0+8)*132 + col0+1] = acc[mt][nt][3];
        }
    }
    __syncthreads();

    #pragma unroll
    for (int i = 0; i < 16; i++) {
        int cell = i*128 + tid;
        int b_l = cell >> 5, hh_l = cell & 31;
        int b = bm + b_l, hh = hh0 + hh_l;
        const float* xrow = Xg + (size_t)(b*L_ + t)*(4*H_);
        float gi = Cs[b_l*132 + 0*32 + hh_l] + xrow[hh]        + bhh[hh];
        float gf = Cs[b_l*132 + 1*32 + hh_l] + xrow[H_+hh]     + bhh[H_+hh];
        float gc = Cs[b_l*132 + 2*32 + hh_l] + xrow[2*H_+hh]   + bhh[2*H_+hh];
        float go = Cs[b_l*132 + 3*32 + hh_l] + xrow[3*H_+hh]   + bhh[3*H_+hh];
        size_t idx = (size_t)b*H_ + hh;
        if (t < lengths[b]) {
            float cn = sigmoidf_(gf)*cst[idx] + sigmoidf_(gi)*tanhf(gc);
            cst[idx] = cn;
            hout[idx] = sigmoidf_(go)*tanhf(cn);
        } else {
            hout[idx] = hin[idx];
        }
    }
}

// ---------------- fused decoder RNN + attention ----------------
__global__ void __launch_bounds__(256)
dec_attn_k(const float* __restrict__ Q,
           const float* __restrict__ WihT,
           const float* __restrict__ WhhT,
           const float* __restrict__ bih, const float* __restrict__ bhh,
           const float* __restrict__ Vt,
           const int* __restrict__ lengths,
           float* __restrict__ R)
{
    int b = blockIdx.x, tid = threadIdx.x;
    __shared__ float shh[H_], sQ[H_], sh[H_];
    __shared__ float sV[L_][H_];
    __shared__ float sHins[STEPS_][H_];
    __shared__ float satt[STEPS_][L_];

    shh[tid] = Q[(size_t)b*H_ + tid];
    for (int i = tid; i < L_*H_; i += 256) sV[i>>8][i&255] = Vt[(size_t)b*L_*H_ + i];
    __syncthreads();

    float acc = bih[tid];
    #pragma unroll 8
    for (int k = 0; k < H_; k++) acc = fmaf(shh[k], WihT[(size_t)k*H_ + tid], acc);
    sQ[tid] = acc;
    sh[tid] = 0.f;
    __syncthreads();

    for (int s = 0; s < STEPS_; s++) {
        float v = sQ[tid] + bhh[tid];
        #pragma unroll 8
        for (int k = 0; k < H_; k++) v = fmaf(sh[k], WhhT[(size_t)k*H_ + tid], v);
        v = fmaxf(v, 0.f);
        __syncthreads();
        sh[tid] = v;
        sHins[s][tid] = v;
        __syncthreads();
    }

    int warp = tid >> 5, lane = tid & 31;
    for (int pid = warp; pid < STEPS_*L_; pid += 8) {
        int s = pid >> 4, l = pid & 15;
        float a = 0.f;
        #pragma unroll
        for (int q = 0; q < H_/32; q++) a = fmaf(sHins[s][lane+32*q], sV[l][lane+32*q], a);
        a = warp_sum(a);
        if (lane == 0) satt[s][l] = a;
    }
    __syncthreads();
    if (tid < STEPS_) {
        int len = lengths[b];
        float m = -3.4e38f;
        for (int l = 0; l < len; l++) m = fmaxf(m, satt[tid][l]);
        float s = 0.f;
        for (int l = 0; l < len; l++) { float e = expf(satt[tid][l]-m); satt[tid][l]=e; s+=e; }
        float inv = 1.f/s;
        for (int l = 0; l < L_; l++) satt[tid][l] = (l < len) ? satt[tid][l]*inv : 0.f;
    }
    __syncthreads();
    for (int s = 0; s < STEPS_; s++) {
        float a2 = 0.f;
        #pragma unroll
        for (int l = 0; l < L_; l++) a2 = fmaf(satt[s][l], sV[l][tid], a2);
        R[((size_t)b*STEPS_ + s)*H_ + tid] = a2;
    }
}

// ---------------- small kernels ----------------
__global__ void build_c_k(const float* __restrict__ vocab, const float* __restrict__ de,
                          float* __restrict__ Cc) {
    int i = blockIdx.x*256 + threadIdx.x;
    if (i < (V_+1)*H_) Cc[i] = (i < V_*H_) ? vocab[i] : de[i - (size_t)V_*H_];
}

__global__ void transpose_wn_k(const float* __restrict__ W, float* __restrict__ WT) {
    __shared__ float t[32][33];
    int rb = blockIdx.y*32, cb = blockIdx.x*32;
    int x = threadIdx.x, y = threadIdx.y;
    for (int j = y; j < 32; j += 8) t[j][x] = W[(size_t)(rb+j)*H_ + cb + x];
    __syncthreads();
    for (int j = y; j < 32; j += 8) WT[(size_t)(cb+j)*H_ + rb + x] = t[x][j];
}

__global__ void vocab_t_k(const float* __restrict__ vocab, float* __restrict__ vt) {
    __shared__ float t[32][33];
    int vb = blockIdx.x*32, hb = blockIdx.y*32;
    int x = threadIdx.x, y = threadIdx.y;
    for (int j = y; j < 32; j += 8) {
        int v = vb + j;
        t[j][x] = (v < V_) ? vocab[(size_t)v*H_ + hb + x] : 0.f;
    }
    __syncthreads();
    for (int j = y; j < 32; j += 8) {
        int v = vb + x;
        if (v < LDLOG_) vt[(size_t)(hb+j)*LDLOG_ + v] = t[x][j];
    }
}

__global__ void zero_k(float* __restrict__ p, int n) {
    int i = blockIdx.x*256 + threadIdx.x;
    if (i < n) p[i] = 0.f;
}

__global__ void row_softmax_w_k(float* __restrict__ Lg) {
    int r = blockIdx.x;
    float* row = Lg + (size_t)r*LDLOG_;
    __shared__ float red[256];
    float m = -3.4e38f;
    for (int j = threadIdx.x; j < V_+1; j += 256) m = fmaxf(m, row[j]);
    red[threadIdx.x] = m; __syncthreads();
    for (int o = 128; o > 0; o >>= 1) {
        if (threadIdx.x < o) red[threadIdx.x] = fmaxf(red[threadIdx.x], red[threadIdx.x+o]);
        __syncthreads();
    }
    float M = red[0]; __syncthreads();
    float s = 0.f;
    for (int j = threadIdx.x; j < V_+1; j += 256) {
        float e = expf(row[j] - M);
        row[j] = e;
        s += e;
    }
    red[threadIdx.x] = s; __syncthreads();
    for (int o = 128; o > 0; o >>= 1) {
        if (threadIdx.x < o) red[threadIdx.x] += red[threadIdx.x+o];
        __syncthreads();
    }
    float inv = 1.f/red[0];
    for (int j = threadIdx.x; j < V_+1; j += 256)
        row[j] *= inv;
}

__global__ void vtag_init_k(const float* __restrict__ words, const float* __restrict__ Lg,
                            float* __restrict__ Vt) {
    int i = blockIdx.x*256 + threadIdx.x;
    int r = i >> 8;
    float w = Lg[(size_t)r*LDLOG_ + V_];
    Vt[i] = w * words[i];
}

__global__ void __launch_bounds__(128)
prop_all_k(const float* __restrict__ R, const float* __restrict__ pe,
           float* __restrict__ ps4) {
    int b = blockIdx.x, s = blockIdx.y;
    int p = threadIdx.x >> 5, lane = threadIdx.x & 31;
    const float* instr = R + ((size_t)b*STEPS_ + s)*H_;
    float acc = 0.f;
    for (int h = lane; h < H_; h += 32) acc = fmaf(instr[h], pe[p*H_ + h], acc);
    acc = warp_sum(acc);
    __shared__ float s4[P_];
    if (lane == 0) s4[p] = acc;
    __syncthreads();
    if (threadIdx.x == 0) {
        float m = fmaxf(fmaxf(s4[0], s4[1]), fmaxf(s4[2], s4[3]));
        float e0 = expf(s4[0]-m), e1 = expf(s4[1]-m), e2 = expf(s4[2]-m), e3 = expf(s4[3]-m);
        float inv = 1.f/(e0+e1+e2+e3);
        float* o = ps4 + ((size_t)b*STEPS_ + s)*P_;
        o[0]=e0*inv; o[1]=e1*inv; o[2]=e2*inv; o[3]=e3*inv;
    }
}

#define NODE_BLKS (N_/8)
#define EDGE_BLKS (E_/8)
__global__ void __launch_bounds__(256)
scores_k(const float* __restrict__ Tr, const float* __restrict__ Et,
         const float* __restrict__ R, const float* __restrict__ ps4,
         const float* __restrict__ Wst, const float* __restrict__ Wrel,
         const int* __restrict__ ng, const int* __restrict__ eg,
         float* __restrict__ ns4, float* __restrict__ es4) {
    int bid = blockIdx.x;
    int warp = threadIdx.x >> 5, lane = threadIdx.x & 31;
    if (bid < NODE_BLKS) {
        int n = bid*8 + warp;
        int g = ng[n];
        const float* T = Tr + (size_t)n*3*H_;
        float t0[8], t1[8], t2[8], ws[8];
        #pragma unroll
        for (int q = 0; q < 8; q++) {
            int h = lane + 32*q;
            t0[q] = T[h]; t1[q] = T[H_+h]; t2[q] = T[2*H_+h]; ws[q] = Wst[h];
        }
        float out[STEPS_];
        #pragma unroll
        for (int s = 0; s < STEPS_; s++) {
            const float* pp = ps4 + ((size_t)g*STEPS_ + s)*P_;
            float p0 = pp[0], p1 = pp[1], p2 = pp[2];
            const float* instr = R + ((size_t)g*STEPS_ + s)*H_;
            float acc = 0.f;
            #pragma unroll
            for (int q = 0; q < 8; q++) {
                int h = lane + 32*q;
                float tv = p0*t0[q] + p1*t1[q] + p2*t2[q];
                float x = instr[h]*tv;
                float e = (x > 0.f) ? x : expm1f(x);
                acc = fmaf(e, ws[q], acc);
            }
            out[s] = warp_sum(acc);
        }
        if (lane == 0)
            *reinterpret_cast<float4*>(ns4 + (size_t)n*4) =
                make_float4(out[0], out[1], out[2], out[3]);
    } else {
        int e = (bid - NODE_BLKS)*8 + warp;
        int g = eg[e];
        const float* et = Et + (size_t)e*H_;
        float ev[8], wr[8];
        #pragma unroll
        for (int q = 0; q < 8; q++) {
            int h = lane + 32*q;
            ev[q] = et[h]; wr[q] = Wrel[h];
        }
        float out[STEPS_];
        #pragma unroll
        for (int s = 0; s < STEPS_; s++) {
            const float* instr = R + ((size_t)g*STEPS_ + s)*H_;
            float acc = 0.f;
            #pragma unroll
            for (int q = 0; q < 8; q++) {
                int h = lane + 32*q;
                float x = instr[h]*ev[q];
                float el = (x > 0.f) ? x : expm1f(x);
                acc = fmaf(el, wr[q], acc);
            }
            out[s] = warp_sum(acc);
        }
        if (lane == 0)
            *reinterpret_cast<float4*>(es4 + (size_t)e*4) =
                make_float4(out[0], out[1], out[2], out[3]);
    }
}

__global__ void __launch_bounds__(256)
graph_loop_k(const float* __restrict__ ns4, const float* __restrict__ es4,
             const float* __restrict__ ps4,
             const int* __restrict__ esrc, const int* __restrict__ edst,
             float* __restrict__ dist_out) {
    int g = blockIdx.x, tid = threadIdx.x;
    __shared__ float dist[NPG_], agg[NPG_], red[256];
    __shared__ int lsrc[EPG_], ldst[EPG_];
    __shared__ float4 ns[NPG_];

    int nbase = g*NPG_, ebase = g*EPG_;
    for (int e = tid; e < EPG_; e += 256) {
        lsrc[e] = esrc[ebase + e] - nbase;
        ldst[e] = edst[ebase + e] - nbase;
    }
    if (tid < NPG_) {
        dist[tid] = 1.f/(float)NPG_;
        ns[tid] = *reinterpret_cast<const float4*>(ns4 + (size_t)(nbase + tid)*4);
    }
    __syncthreads();

    for (int s = 0; s < STEPS_; s++) {
        if (tid < NPG_) agg[tid] = 0.f;
        __syncthreads();
        for (int e = tid; e < EPG_; e += 256) {
            float sc = es4[(size_t)(ebase + e)*4 + s];
            atomicAdd(&agg[ldst[e]], dist[lsrc[e]]*sc);
        }
        __syncthreads();

        float nsv = (tid < NPG_) ? ((const float*)&ns[tid])[s] : -3.4e38f;
        float agv = (tid < NPG_) ? agg[tid] : -3.4e38f;
        red[tid] = nsv; __syncthreads();
        for (int o = 128; o > 0; o >>= 1) { if (tid < o) red[tid] = fmaxf(red[tid], red[tid+o]); __syncthreads(); }
        float m1 = red[0]; __syncthreads();
        red[tid] = agv; __syncthreads();
        for (int o = 128; o > 0; o >>= 1) { if (tid < o) red[tid] = fmaxf(red[tid], red[tid+o]); __syncthreads(); }
        float m2 = red[0]; __syncthreads();
        float e1 = (tid < NPG_) ? expf(nsv - m1) : 0.f;
        float e2 = (tid < NPG_) ? expf(agv - m2) : 0.f;
        red[tid] = e1; __syncthreads();
        for (int o = 128; o > 0; o >>= 1) { if (tid < o) red[tid] += red[tid+o]; __syncthreads(); }
        float s1 = red[0]; __syncthreads();
        red[tid] = e2; __syncthreads();
        for (int o = 128; o > 0; o >>= 1) { if (tid < o) red[tid] += red[tid+o]; __syncthreads(); }
        float s2 = red[0]; __syncthreads();
        if (tid < NPG_) {
            float r = ps4[((size_t)g*STEPS_ + s)*P_ + 3];
            dist[tid] = r*(e2/s2) + (1.f - r)*(e1/s1);
        }
        __syncthreads();
    }
    if (tid < NPG_) dist_out[nbase + tid] = dist[tid];
}

__global__ void final_agg_qa_k(const float* __restrict__ na, const float* __restrict__ ps4,
                               const float* __restrict__ dist, const float* __restrict__ Q,
                               float* __restrict__ QA) {
    int g = blockIdx.x, h = threadIdx.x;
    const float* pp = ps4 + ((size_t)g*STEPS_ + (STEPS_-1))*P_;
    float p0 = pp[0], p1 = pp[1], p2 = pp[2];
    float acc = 0.f;
    for (int i = 0; i < NPG_; i++) {
        size_t n = (size_t)g*NPG_ + i;
        const float* a = na + n*3*H_;
        float nf = p0*a[h] + p1*a[H_+h] + p2*a[2*H_+h];
        acc = fmaf(dist[n], nf, acc);
    }
    QA[(size_t)g*2*H_ + h]      = Q[(size_t)g*H_ + h];
    QA[(size_t)g*2*H_ + H_ + h] = acc;
}

// ---------------- launchers ----------------
static inline void tc_gemm(cudaStream_t st,
                           const float* A, int lda, const float* Bm, int ldb,
                           float* C, int ldc, int M, int N, int K,
                           const float* bias, int splitk = 1) {
    dim3 g((N + GB_N - 1)/GB_N, (M + GB_M - 1)/GB_M, splitk);
    mma_gemm_k<<<g, 128, G_SMEM_BYTES, st>>>(A, lda, Bm, ldb, C, ldc, M, N, K, bias, splitk);
}

extern "C" void kernel_launch(void* const* d_in, const int* in_sizes, int n_in,
                              void* d_out, int out_size) {
    const float* questions     = (const float*)d_in[0];
    const float* node_attrs    = (const float*)d_in[1];
    const float* edge_attrs    = (const float*)d_in[2];
    const float* vocab         = (const float*)d_in[3];
    const float* default_embed = (const float*)d_in[4];
    const float* W_norm        = (const float*)d_in[5];
    const float* lstm_Wih      = (const float*)d_in[6];
    const float* lstm_Whh      = (const float*)d_in[7];
    const float* lstm_bih      = (const float*)d_in[8];
    const float* lstm_bhh      = (const float*)d_in[9];
    const float* rnn_Wih       = (const float*)d_in[10];
    const float* rnn_Whh       = (const float*)d_in[11];
    const float* rnn_bih       = (const float*)d_in[12];
    const float* rnn_bhh       = (const float*)d_in[13];
    const float* prop_embeds   = (const float*)d_in[14];
    const float* Ws_property   = (const float*)d_in[15];
    const float* W_state       = (const float*)d_in[16];
    const float* W_relation    = (const float*)d_in[17];
    const float* lin_W         = (const float*)d_in[18];
    const float* lin_b         = (const float*)d_in[19];
    const int*   lengths       = (const int*)d_in[20];
    const int*   node_graph    = (const int*)d_in[21];
    const int*   edge_graph    = (const int*)d_in[22];
    const int*   edge_src      = (const int*)d_in[23];
    const int*   edge_dst      = (const int*)d_in[24];
    float* out = (float*)d_out;

    cudaFuncSetAttribute(mma_gemm_k, cudaFuncAttributeMaxDynamicSharedMemorySize, G_SMEM_BYTES);
    cudaFuncSetAttribute(lstm_mma_k, cudaFuncAttributeMaxDynamicSharedMemorySize, L_SMEM_BYTES);

    float* S = nullptr;
    cudaGetSymbolAddress((void**)&S, g_scratch);
    float* Cc   = S + OFF_C;
    float* XW   = S + OFF_XW;
    float* LG   = S + OFF_LOG;
    float* VT   = S + OFF_VT;
    float* XG   = S + OFF_XG;
    float* H0   = S + OFF_H;
    float* Cst  = S + OFF_CS;
    float* H1   = S + OFF_H2;
    float* Rr   = S + OFF_R;
    float* PS4  = S + OFF_PS;
    float* TR   = S + OFF_TR;
    float* ET   = S + OFF_ET;
    float* NS4  = S + OFF_NS4;
    float* ES4  = S + OFF_ES4;
    float* DIST = S + OFF_DIST;
    float* QA   = S + OFF_QA;
    float* WNT  = S + OFF_WNT;
    float* VOCT = S + OFF_VOCT;
    float* WIHT = S + OFF_WIHT;
    float* WHHT = S + OFF_WHHT;

    cudaStream_t s0 = 0;      // capture/default stream
    cudaStream_t s2;
    cudaEvent_t ev_fork, ev_join;
    cudaStreamCreateWithFlags(&s2, cudaStreamNonBlocking);
    cudaEventCreateWithFlags(&ev_fork, cudaEventDisableTiming);
    cudaEventCreateWithFlags(&ev_join, cudaEventDisableTiming);

    // fork s2 off the capture stream (graph-capture-safe)
    cudaEventRecord(ev_fork, s0);
    cudaStreamWaitEvent(s2, ev_fork, 0);

    // ---- stream 2: graph transforms (depend only on raw inputs, 35 GF) ----
    for (int p = 0; p < 3; p++)
        tc_gemm(s2, node_attrs + p*H_, 3*H_, Ws_property + (size_t)p*H_*H_, H_,
                TR + p*H_, 3*H_, N_, H_, H_, nullptr);
    tc_gemm(s2, edge_attrs, H_, Ws_property + (size_t)3*H_*H_, H_, ET, H_, E_, H_, H_, nullptr);
    cudaEventRecord(ev_join, s2);

    // ---- stream 0: main chain ----
    build_c_k<<<((V_+1)*H_ + 255)/256, 256, 0, s0>>>(vocab, default_embed, Cc);
    transpose_wn_k<<<dim3(8,8), dim3(32,8), 0, s0>>>(W_norm, WNT);
    transpose_wn_k<<<dim3(8,8), dim3(32,8), 0, s0>>>(rnn_Wih, WIHT);
    transpose_wn_k<<<dim3(8,8), dim3(32,8), 0, s0>>>(rnn_Whh, WHHT);
    vocab_t_k<<<dim3((LDLOG_+31)/32, H_/32), dim3(32,8), 0, s0>>>(vocab, VOCT);

    tc_gemm(s0, questions, H_, WNT, H_, XW, H_, BL_, H_, H_, nullptr);
    tc_gemm(s0, XW, H_, Cc, H_, LG, LDLOG_, BL_, V_+1, H_, nullptr);
    row_softmax_w_k<<<BL_, 256, 0, s0>>>(LG);
    vtag_init_k<<<BL_*H_/256, 256, 0, s0>>>(questions, LG, VT);
    tc_gemm(s0, LG, LDLOG_, VOCT, LDLOG_, VT, H_, BL_, H_, V_, nullptr, 4);

    tc_gemm(s0, VT, H_, lstm_Wih, H_, XG, 4*H_, BL_, 4*H_, H_, lstm_bih);
    zero_k<<<(2*B_*H_ + 255)/256, 256, 0, s0>>>(H0, 2*B_*H_);
    for (int t = 0; t < L_; t++) {
        const float* hin = (t & 1) ? H1 : H0;
        float* hout      = (t & 1) ? H0 : H1;
        lstm_mma_k<<<dim3(H_/32, B_/64), 128, L_SMEM_BYTES, s0>>>(hin, hout, Cst, XG,
                                                                  lstm_Whh, lstm_bhh, lengths, t);
    }

    dec_attn_k<<<B_, 256, 0, s0>>>(H0, WIHT, WHHT, rnn_bih, rnn_bhh, VT, lengths, Rr);
    prop_all_k<<<dim3(B_, STEPS_), 128, 0, s0>>>(Rr, prop_embeds, PS4);

    // join: scores needs TR/ET from s2
    cudaStreamWaitEvent(s0, ev_join, 0);
    scores_k<<<NODE_BLKS + EDGE_BLKS, 256, 0, s0>>>(TR, ET, Rr, PS4, W_state, W_relation,
                                                    node_graph, edge_graph, NS4, ES4);
    graph_loop_k<<<B_, 256, 0, s0>>>(NS4, ES4, PS4, edge_src, edge_dst, DIST);

    final_agg_qa_k<<<B_, 256, 0, s0>>>(node_attrs, PS4, DIST, H0, QA);
    zero_k<<<(B_*OUT_ + 255)/256, 256, 0, s0>>>(out, B_*OUT_);
    tc_gemm(s0, QA, 2*H_, lin_W, 2*H_, out, OUT_, B_, OUT_, 2*H_, lin_b, 4);

    cudaStreamDestroy(s2);
    cudaEventDestroy(ev_fork);
    cudaEventDestroy(ev_join);
}

// round 16
// speedup vs baseline: 1.3416x; 1.1892x over previous
#include <cuda_runtime.h>
#include <cuda_fp16.h>
#include <math.h>
#include <stdint.h>

#define B_      256
#define L_      16
#define H_      256
#define V_      5000
#define P_      4
#define NPG_    150
#define DEG_    4
#define EPG_    (NPG_*DEG_)
#define STEPS_  4
#define OUT_    2000
#define N_      (B_*NPG_)
#define E_      (N_*DEG_)
#define BL_     (B_*L_)
#define LDLOG_  5008

// ---------------- scratch arena (sizes in floats; half buffers use n/2) ----------------
static constexpr size_t OFF_CCH   = 0;                                          // half (V+1)*H
static constexpr size_t OFF_XWH   = OFF_CCH   + (size_t)(V_+1)*H_/2;            // half BL*H
static constexpr size_t OFF_LOG   = OFF_XWH   + (size_t)BL_*H_/2;               // float BL*LDLOG
static constexpr size_t OFF_LGH   = OFF_LOG   + (size_t)BL_*LDLOG_;             // half BL*LDLOG
static constexpr size_t OFF_VT    = OFF_LGH   + (size_t)BL_*LDLOG_/2;           // float BL*H
static constexpr size_t OFF_VTH   = OFF_VT    + (size_t)BL_*H_;                 // half BL*H
static constexpr size_t OFF_XG    = OFF_VTH   + (size_t)BL_*H_/2;               // float BL*4H
static constexpr size_t OFF_H0H   = OFF_XG    + (size_t)BL_*4*H_;               // half B*H
static constexpr size_t OFF_H1H   = OFF_H0H   + (size_t)B_*H_/2;                // half B*H
static constexpr size_t OFF_CS    = OFF_H1H   + (size_t)B_*H_/2;                // float B*H
static constexpr size_t OFF_R     = OFF_CS    + (size_t)B_*H_;                  // float B*4*H
static constexpr size_t OFF_PS    = OFF_R     + (size_t)B_*STEPS_*H_;           // float B*16
static constexpr size_t OFF_TR    = OFF_PS    + (size_t)B_*STEPS_*P_;           // float N*3H
static constexpr size_t OFF_ET    = OFF_TR    + (size_t)N_*3*H_;                // float E*H
static constexpr size_t OFF_NS4   = OFF_ET    + (size_t)E_*H_;
static constexpr size_t OFF_ES4   = OFF_NS4   + (size_t)N_*4;
static constexpr size_t OFF_DIST  = OFF_ES4   + (size_t)E_*4;
static constexpr size_t OFF_QAH   = OFF_DIST  + (size_t)N_;                     // half B*2H
static constexpr size_t OFF_WNTH  = OFF_QAH   + (size_t)B_*2*H_/2;              // half H*H
static constexpr size_t OFF_VOCTH = OFF_WNTH  + (size_t)H_*H_/2;                // half H*LDLOG
static constexpr size_t OFF_WIHT  = OFF_VOCTH + (size_t)H_*LDLOG_/2;            // float H*H
static constexpr size_t OFF_WHHT  = OFF_WIHT  + (size_t)H_*H_;                  // float H*H
static constexpr size_t OFF_QH    = OFF_WHHT  + (size_t)H_*H_;                  // half BL*H
static constexpr size_t OFF_WIHH  = OFF_QH    + (size_t)BL_*H_/2;               // half 4H*H
static constexpr size_t OFF_WHHH  = OFF_WIHH  + (size_t)4*H_*H_/2;              // half 4H*H
static constexpr size_t OFF_NAH   = OFF_WHHH  + (size_t)4*H_*H_/2;              // half N*3H
static constexpr size_t OFF_EAH   = OFF_NAH   + (size_t)N_*3*H_/2;              // half E*H
static constexpr size_t OFF_WSH   = OFF_EAH   + (size_t)E_*H_/2;                // half P*H*H
static constexpr size_t OFF_LWH   = OFF_WSH   + (size_t)P_*H_*H_/2;             // half OUT*2H
static constexpr size_t TOTAL_SCRATCH = OFF_LWH + (size_t)OUT_*2*H_/2;

__device__ __align__(16) float g_scratch[TOTAL_SCRATCH];

// ---------------- helpers ----------------
__device__ __forceinline__ float warp_sum(float v) {
    #pragma unroll
    for (int o = 16; o > 0; o >>= 1) v += __shfl_down_sync(0xffffffffu, v, o);
    return v;
}
__device__ __forceinline__ float sigmoidf_(float x) { return 1.f / (1.f + expf(-x)); }
__device__ __forceinline__ uint32_t smem_u32(const void* p) {
    uint32_t a;
    asm("{ .reg .u64 t; cvta.to.shared.u64 t, %1; cvt.u32.u64 %0, t; }" : "=r"(a) : "l"(p));
    return a;
}
__device__ __forceinline__ void cp_async16(void* sdst, const void* gsrc, bool pred) {
    uint32_t d = smem_u32(sdst);
    int sz = pred ? 16 : 0;
    asm volatile("cp.async.cg.shared.global [%0], [%1], 16, %2;"
                 :: "r"(d), "l"(gsrc), "r"(sz));
}
__device__ __forceinline__ void cp_commit() {
    asm volatile("cp.async.commit_group;" ::: "memory");
}
template<int N>
__device__ __forceinline__ void cp_wait() {
    asm volatile("cp.async.wait_group %0;" :: "n"(N) : "memory");
}
__device__ __forceinline__ void mma_f16(float* d, const uint32_t* a, const uint32_t* b) {
    asm volatile(
        "mma.sync.aligned.m16n8k16.row.col.f32.f16.f16.f32 "
        "{%0,%1,%2,%3}, {%4,%5,%6,%7}, {%8,%9}, {%0,%1,%2,%3};"
        : "+f"(d[0]), "+f"(d[1]), "+f"(d[2]), "+f"(d[3])
        : "r"(a[0]), "r"(a[1]), "r"(a[2]), "r"(a[3]), "r"(b[0]), "r"(b[1]));
}

// ---------------- fp16 GEMM: CTA 128x128xK64, 128 thr, warp 64x64 ----------------
// C[m,n] = sum_k A[m,k]*B[n,k] (+bias[n]); fp32 accumulate; HOUT: store __half.
#define HB_K 64
#define HTS  72
#define HABUF (128*HTS)
#define HBBUF (128*HTS)
#define H_SMEM_BYTES ((2*HABUF + 2*HBBUF)*2)

template<bool HOUT>
__global__ void __launch_bounds__(128, 2)
mma_gemm_h(const __half* __restrict__ A, int lda,
           const __half* __restrict__ Bm, int ldb,
           void* __restrict__ Cv, int ldc,
           int M, int N, int K, const float* __restrict__ bias, int splitk)
{
    extern __shared__ float smf[];
    __half* As = reinterpret_cast<__half*>(smf);
    __half* Bs = As + 2*HABUF;
    const int tid  = threadIdx.x;
    const int wid  = tid >> 5, lane = tid & 31;
    const int g    = lane >> 2, t4 = lane & 3;
    const int wm   = wid & 1, wn = wid >> 1;
    const int bm   = blockIdx.y * 128;
    const int bn   = blockIdx.x * 128;

    int kbeg = 0, kend = K;
    if (splitk > 1) {
        int kslen = (((K + splitk - 1) / splitk) + 7) & ~7;
        kbeg = blockIdx.z * kslen;
        kend = min(K, kbeg + kslen);
    }

    float acc[4][8][4];
    #pragma unroll
    for (int i = 0; i < 4; i++)
        #pragma unroll
        for (int j = 0; j < 8; j++)
            #pragma unroll
            for (int q = 0; q < 4; q++) acc[i][j][q] = 0.f;

    const int lrow = tid >> 3, lc8 = (tid & 7) << 3;   // 16 rows/pass, granule 8 halves

    auto issue_chunk = [&](int c) {
        int k0 = kbeg + c * HB_K;
        int buf = c & 1;
        #pragma unroll
        for (int i = 0; i < 8; i++) {
            int row = lrow + i*16;
            int gm = bm + row, gk = k0 + lc8;
            cp_async16(As + buf*HABUF + row*HTS + lc8,
                       A + (size_t)gm*lda + gk, (gm < M) && (gk < kend));
        }
        #pragma unroll
        for (int i = 0; i < 8; i++) {
            int row = lrow + i*16;
            int gn = bn + row, gk = k0 + lc8;
            cp_async16(Bs + buf*HBBUF + row*HTS + lc8,
                       Bm + (size_t)gn*ldb + gk, (gn < N) && (gk < kend));
        }
        cp_commit();
    };

    const int nch = (kend - kbeg + HB_K - 1) / HB_K;
    issue_chunk(0);

    for (int c = 0; c < nch; c++) {
        if (c + 1 < nch) { issue_chunk(c + 1); cp_wait<1>(); }
        else             { cp_wait<0>(); }
        __syncthreads();

        const __half* Ab = As + (c & 1)*HABUF;
        const __half* Bb = Bs + (c & 1)*HBBUF;
        #pragma unroll
        for (int ks = 0; ks < 4; ks++) {           // 4 x k16 per 64-chunk
            int kh = ks*16;
            uint32_t af[4][4], bf[8][2];
            #pragma unroll
            for (int mt = 0; mt < 4; mt++) {
                int r0 = (wm*64 + mt*16 + g)*HTS + kh + 2*t4;
                af[mt][0] = *reinterpret_cast<const uint32_t*>(Ab + r0);
                af[mt][1] = *reinterpret_cast<const uint32_t*>(Ab + r0 + 8*HTS);
                af[mt][2] = *reinterpret_cast<const uint32_t*>(Ab + r0 + 8);
                af[mt][3] = *reinterpret_cast<const uint32_t*>(Ab + r0 + 8*HTS + 8);
            }
            #pragma unroll
            for (int nt = 0; nt < 8; nt++) {
                int rb = (wn*64 + nt*8 + g)*HTS + kh + 2*t4;
                bf[nt][0] = *reinterpret_cast<const uint32_t*>(Bb + rb);
                bf[nt][1] = *reinterpret_cast<const uint32_t*>(Bb + rb + 8);
            }
            #pragma unroll
            for (int mt = 0; mt < 4; mt++)
                #pragma unroll
                for (int nt = 0; nt < 8; nt++)
                    mma_f16(acc[mt][nt], af[mt], bf[nt]);
        }
        __syncthreads();
    }

    float* Cf = (float*)Cv;
    __half* Ch = (__half*)Cv;
    const bool addb = (bias != nullptr) && (blockIdx.z == 0);
    #pragma unroll
    for (int mt = 0; mt < 4; mt++) {
        int row0 = bm + wm*64 + mt*16 + g;
        #pragma unroll
        for (int nt = 0; nt < 8; nt++) {
            int col0 = bn + wn*64 + nt*8 + t4*2;
            float b0v = 0.f, b1v = 0.f;
            if (addb) {
                if (col0     < N) b0v = bias[col0];
                if (col0 + 1 < N) b1v = bias[col0+1];
            }
            float v0 = acc[mt][nt][0] + b0v, v1 = acc[mt][nt][1] + b1v;
            float v2 = acc[mt][nt][2] + b0v, v3 = acc[mt][nt][3] + b1v;
            if (splitk > 1) {
                if (row0 < M) {
                    if (col0     < N) atomicAdd(&Cf[(size_t)row0*ldc + col0    ], v0);
                    if (col0 + 1 < N) atomicAdd(&Cf[(size_t)row0*ldc + col0 + 1], v1);
                }
                if (row0 + 8 < M) {
                    if (col0     < N) atomicAdd(&Cf[(size_t)(row0+8)*ldc + col0    ], v2);
                    if (col0 + 1 < N) atomicAdd(&Cf[(size_t)(row0+8)*ldc + col0 + 1], v3);
                }
            } else if (HOUT) {
                if (row0 < M) {
                    if (col0     < N) Ch[(size_t)row0*ldc + col0    ] = __float2half(v0);
                    if (col0 + 1 < N) Ch[(size_t)row0*ldc + col0 + 1] = __float2half(v1);
                }
                if (row0 + 8 < M) {
                    if (col0     < N) Ch[(size_t)(row0+8)*ldc + col0    ] = __float2half(v2);
                    if (col0 + 1 < N) Ch[(size_t)(row0+8)*ldc + col0 + 1] = __float2half(v3);
                }
            } else {
                if (row0 < M) {
                    if (col0     < N) Cf[(size_t)row0*ldc + col0    ] = v0;
                    if (col0 + 1 < N) Cf[(size_t)row0*ldc + col0 + 1] = v1;
                }
                if (row0 + 8 < M) {
                    if (col0     < N) Cf[(size_t)(row0+8)*ldc + col0    ] = v2;
                    if (col0 + 1 < N) Cf[(size_t)(row0+8)*ldc + col0 + 1] = v3;
                }
            }
        }
    }
}

// ---------------- fp16 fused LSTM step: CTA 64 x 128(gathered), 128 thr ----------------
#define LHABUF (64*HTS)
#define LHBBUF (128*HTS)
#define LH_SMEM_BYTES ((2*LHABUF + 2*LHBBUF)*2)   // 55296; Cs floats (64*132*4=33792) reuse

__global__ void __launch_bounds__(128, 2)
lstm_mma_h(const __half* __restrict__ hin,
           __half* __restrict__ hout,
           float* __restrict__ cst,
           const float* __restrict__ Xg,
           const __half* __restrict__ Whh,
           const float* __restrict__ bhh,
           const int* __restrict__ lengths, int t)
{
    extern __shared__ float smf[];
    __half* As = reinterpret_cast<__half*>(smf);
    __half* Bs = As + 2*LHABUF;
    float*  Cs = smf;
    const int tid = threadIdx.x;
    const int wid = tid >> 5, lane = tid & 31;
    const int g   = lane >> 2, t4 = lane & 3;
    const int wm  = wid & 1, wn = wid >> 1;
    const int hh0 = blockIdx.x * 32;
    const int bm  = blockIdx.y * 64;

    float acc[2][8][4];
    #pragma unroll
    for (int i = 0; i < 2; i++)
        #pragma unroll
        for (int j = 0; j < 8; j++)
            #pragma unroll
            for (int q = 0; q < 4; q++) acc[i][j][q] = 0.f;

    const int lrow = tid >> 3, lc8 = (tid & 7) << 3;

    auto issue_chunk = [&](int c) {
        int k0 = c * HB_K;
        int buf = c & 1;
        #pragma unroll
        for (int i = 0; i < 4; i++) {
            int row = lrow + i*16;
            cp_async16(As + buf*LHABUF + row*HTS + lc8,
                       hin + (size_t)(bm + row)*H_ + k0 + lc8, true);
        }
        #pragma unroll
        for (int i = 0; i < 8; i++) {
            int row = lrow + i*16;
            int gn = (row >> 5)*H_ + hh0 + (row & 31);
            cp_async16(Bs + buf*LHBBUF + row*HTS + lc8,
                       Whh + (size_t)gn*H_ + k0 + lc8, true);
        }
        cp_commit();
    };

    const int nch = H_ / HB_K;   // 4
    issue_chunk(0);
    for (int c = 0; c < nch; c++) {
        if (c + 1 < nch) { issue_chunk(c + 1); cp_wait<1>(); }
        else             { cp_wait<0>(); }
        __syncthreads();
        const __half* Ab = As + (c & 1)*LHABUF;
        const __half* Bb = Bs + (c & 1)*LHBBUF;
        #pragma unroll
        for (int ks = 0; ks < 4; ks++) {
            int kh = ks*16;
            uint32_t af[2][4], bf[8][2];
            #pragma unroll
            for (int mt = 0; mt < 2; mt++) {
                int r0 = (wm*32 + mt*16 + g)*HTS + kh + 2*t4;
                af[mt][0] = *reinterpret_cast<const uint32_t*>(Ab + r0);
                af[mt][1] = *reinterpret_cast<const uint32_t*>(Ab + r0 + 8*HTS);
                af[mt][2] = *reinterpret_cast<const uint32_t*>(Ab + r0 + 8);
                af[mt][3] = *reinterpret_cast<const uint32_t*>(Ab + r0 + 8*HTS + 8);
            }
            #pragma unroll
            for (int nt = 0; nt < 8; nt++) {
                int rb = (wn*64 + nt*8 + g)*HTS + kh + 2*t4;
                bf[nt][0] = *reinterpret_cast<const uint32_t*>(Bb + rb);
                bf[nt][1] = *reinterpret_cast<const uint32_t*>(Bb + rb + 8);
            }
            #pragma unroll
            for (int mt = 0; mt < 2; mt++)
                #pragma unroll
                for (int nt = 0; nt < 8; nt++)
                    mma_f16(acc[mt][nt], af[mt], bf[nt]);
        }
        __syncthreads();
    }

    #pragma unroll
    for (int mt = 0; mt < 2; mt++) {
        int row0 = wm*32 + mt*16 + g;
        #pragma unroll
        for (int nt = 0; nt < 8; nt++) {
            int col0 = wn*64 + nt*8 + t4*2;
            Cs[row0*132 + col0]       = acc[mt][nt][0];
            Cs[row0*132 + col0 + 1]   = acc[mt][nt][1];
            Cs[(row0+8)*132 + col0]   = acc[mt][nt][2];
            Cs[(row0+8)*132 + col0+1] = acc[mt][nt][3];
        }
    }
    __syncthreads();

    #pragma unroll
    for (int i = 0; i < 16; i++) {
        int cell = i*128 + tid;
        int b_l = cell >> 5, hh_l = cell & 31;
        int b = bm + b_l, hh = hh0 + hh_l;
        const float* xrow = Xg + (size_t)(b*L_ + t)*(4*H_);
        float gi = Cs[b_l*132 + 0*32 + hh_l] + xrow[hh]        + bhh[hh];
        float gf = Cs[b_l*132 + 1*32 + hh_l] + xrow[H_+hh]     + bhh[H_+hh];
        float gc = Cs[b_l*132 + 2*32 + hh_l] + xrow[2*H_+hh]   + bhh[2*H_+hh];
        float go = Cs[b_l*132 + 3*32 + hh_l] + xrow[3*H_+hh]   + bhh[3*H_+hh];
        size_t idx = (size_t)b*H_ + hh;
        if (t < lengths[b]) {
            float cn = sigmoidf_(gf)*cst[idx] + sigmoidf_(gi)*tanhf(gc);
            cst[idx] = cn;
            hout[idx] = __float2half(sigmoidf_(go)*tanhf(cn));
        } else {
            hout[idx] = hin[idx];
        }
    }
}

// ---------------- fused decoder RNN + attention (Q in fp16) ----------------
__global__ void __launch_bounds__(256)
dec_attn_k(const __half* __restrict__ Q,
           const float* __restrict__ WihT,
           const float* __restrict__ WhhT,
           const float* __restrict__ bih, const float* __restrict__ bhh,
           const float* __restrict__ Vt,
           const int* __restrict__ lengths,
           float* __restrict__ R)
{
    int b = blockIdx.x, tid = threadIdx.x;
    __shared__ float shh[H_], sQ[H_], sh[H_];
    __shared__ float sV[L_][H_];
    __shared__ float sHins[STEPS_][H_];
    __shared__ float satt[STEPS_][L_];

    shh[tid] = __half2float(Q[(size_t)b*H_ + tid]);
    for (int i = tid; i < L_*H_; i += 256) sV[i>>8][i&255] = Vt[(size_t)b*L_*H_ + i];
    __syncthreads();

    float acc = bih[tid];
    #pragma unroll 8
    for (int k = 0; k < H_; k++) acc = fmaf(shh[k], WihT[(size_t)k*H_ + tid], acc);
    sQ[tid] = acc;
    sh[tid] = 0.f;
    __syncthreads();

    for (int s = 0; s < STEPS_; s++) {
        float v = sQ[tid] + bhh[tid];
        #pragma unroll 8
        for (int k = 0; k < H_; k++) v = fmaf(sh[k], WhhT[(size_t)k*H_ + tid], v);
        v = fmaxf(v, 0.f);
        __syncthreads();
        sh[tid] = v;
        sHins[s][tid] = v;
        __syncthreads();
    }

    int warp = tid >> 5, lane = tid & 31;
    for (int pid = warp; pid < STEPS_*L_; pid += 8) {
        int s = pid >> 4, l = pid & 15;
        float a = 0.f;
        #pragma unroll
        for (int q = 0; q < H_/32; q++) a = fmaf(sHins[s][lane+32*q], sV[l][lane+32*q], a);
        a = warp_sum(a);
        if (lane == 0) satt[s][l] = a;
    }
    __syncthreads();
    if (tid < STEPS_) {
        int len = lengths[b];
        float m = -3.4e38f;
        for (int l = 0; l < len; l++) m = fmaxf(m, satt[tid][l]);
        float s = 0.f;
        for (int l = 0; l < len; l++) { float e = expf(satt[tid][l]-m); satt[tid][l]=e; s+=e; }
        float inv = 1.f/s;
        for (int l = 0; l < L_; l++) satt[tid][l] = (l < len) ? satt[tid][l]*inv : 0.f;
    }
    __syncthreads();
    for (int s = 0; s < STEPS_; s++) {
        float a2 = 0.f;
        #pragma unroll
        for (int l = 0; l < L_; l++) a2 = fmaf(satt[s][l], sV[l][tid], a2);
        R[((size_t)b*STEPS_ + s)*H_ + tid] = a2;
    }
}

// ---------------- small kernels ----------------
__global__ void f2h_k(const float* __restrict__ s, __half* __restrict__ d, int n) {
    int i = (blockIdx.x*256 + threadIdx.x)*4;
    if (i < n) {
        float4 v = *reinterpret_cast<const float4*>(s + i);
        *reinterpret_cast<__half2*>(d + i)     = __floats2half2_rn(v.x, v.y);
        *reinterpret_cast<__half2*>(d + i + 2) = __floats2half2_rn(v.z, v.w);
    }
}

__global__ void build_c_h_k(const float* __restrict__ vocab, const float* __restrict__ de,
                            __half* __restrict__ Cc) {
    int i = blockIdx.x*256 + threadIdx.x;
    if (i < (V_+1)*H_) Cc[i] = __float2half((i < V_*H_) ? vocab[i] : de[i - (size_t)V_*H_]);
}

__global__ void transpose_h_k(const float* __restrict__ W, __half* __restrict__ WT) {
    __shared__ float t[32][33];
    int rb = blockIdx.y*32, cb = blockIdx.x*32;
    int x = threadIdx.x, y = threadIdx.y;
    for (int j = y; j < 32; j += 8) t[j][x] = W[(size_t)(rb+j)*H_ + cb + x];
    __syncthreads();
    for (int j = y; j < 32; j += 8) WT[(size_t)(cb+j)*H_ + rb + x] = __float2half(t[x][j]);
}

__global__ void transpose_f_k(const float* __restrict__ W, float* __restrict__ WT) {
    __shared__ float t[32][33];
    int rb = blockIdx.y*32, cb = blockIdx.x*32;
    int x = threadIdx.x, y = threadIdx.y;
    for (int j = y; j < 32; j += 8) t[j][x] = W[(size_t)(rb+j)*H_ + cb + x];
    __syncthreads();
    for (int j = y; j < 32; j += 8) WT[(size_t)(cb+j)*H_ + rb + x] = t[x][j];
}

__global__ void vocab_t_h_k(const float* __restrict__ vocab, __half* __restrict__ vt) {
    __shared__ float t[32][33];
    int vb = blockIdx.x*32, hb = blockIdx.y*32;
    int x = threadIdx.x, y = threadIdx.y;
    for (int j = y; j < 32; j += 8) {
        int v = vb + j;
        t[j][x] = (v < V_) ? vocab[(size_t)v*H_ + hb + x] : 0.f;
    }
    __syncthreads();
    for (int j = y; j < 32; j += 8) {
        int v = vb + x;
        if (v < LDLOG_) vt[(size_t)(hb+j)*LDLOG_ + v] = __float2half(t[x][j]);
    }
}

__global__ void zero_k(float* __restrict__ p, int n) {
    int i = blockIdx.x*256 + threadIdx.x;
    if (i < n) p[i] = 0.f;
}

// smem-resident softmax: read logits once, write fp16 probs once.
__global__ void __launch_bounds__(256)
row_softmax_h_k(const float* __restrict__ Lg, __half* __restrict__ LgH) {
    __shared__ float srow[LDLOG_];
    __shared__ float red[256];
    int r = blockIdx.x, tid = threadIdx.x;
    const float* row = Lg + (size_t)r*LDLOG_;
    float m = -3.4e38f;
    for (int j = tid; j < V_+1; j += 256) {
        float x = row[j];
        srow[j] = x;
        m = fmaxf(m, x);
    }
    red[tid] = m; __syncthreads();
    for (int o = 128; o > 0; o >>= 1) {
        if (tid < o) red[tid] = fmaxf(red[tid], red[tid+o]);
        __syncthreads();
    }
    float M = red[0]; __syncthreads();
    float s = 0.f;
    for (int j = tid; j < V_+1; j += 256) {
        float e = expf(srow[j] - M);
        srow[j] = e;
        s += e;
    }
    red[tid] = s; __syncthreads();
    for (int o = 128; o > 0; o >>= 1) {
        if (tid < o) red[tid] += red[tid+o];
        __syncthreads();
    }
    float inv = 1.f/red[0];
    __half* orow = LgH + (size_t)r*LDLOG_;
    for (int j = tid; j < V_+1; j += 256)
        orow[j] = __float2half(srow[j] * inv);
}

__global__ void vtag_init_k(const float* __restrict__ words, const __half* __restrict__ LgH,
                            float* __restrict__ Vt) {
    int i = blockIdx.x*256 + threadIdx.x;
    int r = i >> 8;
    float w = __half2float(LgH[(size_t)r*LDLOG_ + V_]);
    Vt[i] = w * words[i];
}

__global__ void __launch_bounds__(128)
prop_all_k(const float* __restrict__ R, const float* __restrict__ pe,
           float* __restrict__ ps4) {
    int b = blockIdx.x, s = blockIdx.y;
    int p = threadIdx.x >> 5, lane = threadIdx.x & 31;
    const float* instr = R + ((size_t)b*STEPS_ + s)*H_;
    float acc = 0.f;
    for (int h = lane; h < H_; h += 32) acc = fmaf(instr[h], pe[p*H_ + h], acc);
    acc = warp_sum(acc);
    __shared__ float s4[P_];
    if (lane == 0) s4[p] = acc;
    __syncthreads();
    if (threadIdx.x == 0) {
        float m = fmaxf(fmaxf(s4[0], s4[1]), fmaxf(s4[2], s4[3]));
        float e0 = expf(s4[0]-m), e1 = expf(s4[1]-m), e2 = expf(s4[2]-m), e3 = expf(s4[3]-m);
        float inv = 1.f/(e0+e1+e2+e3);
        float* o = ps4 + ((size_t)b*STEPS_ + s)*P_;
        o[0]=e0*inv; o[1]=e1*inv; o[2]=e2*inv; o[3]=e3*inv;
    }
}

#define NODE_BLKS (N_/8)
#define EDGE_BLKS (E_/8)
__global__ void __launch_bounds__(256)
scores_k(const float* __restrict__ Tr, const float* __restrict__ Et,
         const float* __restrict__ R, const float* __restrict__ ps4,
         const float* __restrict__ Wst, const float* __restrict__ Wrel,
         const int* __restrict__ ng, const int* __restrict__ eg,
         float* __restrict__ ns4, float* __restrict__ es4) {
    int bid = blockIdx.x;
    int warp = threadIdx.x >> 5, lane = threadIdx.x & 31;
    if (bid < NODE_BLKS) {
        int n = bid*8 + warp;
        int g = ng[n];
        const float* T = Tr + (size_t)n*3*H_;
        float t0[8], t1[8], t2[8], ws[8];
        #pragma unroll
        for (int q = 0; q < 8; q++) {
            int h = lane + 32*q;
            t0[q] = T[h]; t1[q] = T[H_+h]; t2[q] = T[2*H_+h]; ws[q] = Wst[h];
        }
        float out[STEPS_];
        #pragma unroll
        for (int s = 0; s < STEPS_; s++) {
            const float* pp = ps4 + ((size_t)g*STEPS_ + s)*P_;
            float p0 = pp[0], p1 = pp[1], p2 = pp[2];
            const float* instr = R + ((size_t)g*STEPS_ + s)*H_;
            float acc = 0.f;
            #pragma unroll
            for (int q = 0; q < 8; q++) {
                int h = lane + 32*q;
                float tv = p0*t0[q] + p1*t1[q] + p2*t2[q];
                float x = instr[h]*tv;
                float e = (x > 0.f) ? x : expm1f(x);
                acc = fmaf(e, ws[q], acc);
            }
            out[s] = warp_sum(acc);
        }
        if (lane == 0)
            *reinterpret_cast<float4*>(ns4 + (size_t)n*4) =
                make_float4(out[0], out[1], out[2], out[3]);
    } else {
        int e = (bid - NODE_BLKS)*8 + warp;
        int g = eg[e];
        const float* et = Et + (size_t)e*H_;
        float ev[8], wr[8];
        #pragma unroll
        for (int q = 0; q < 8; q++) {
            int h = lane + 32*q;
            ev[q] = et[h]; wr[q] = Wrel[h];
        }
        float out[STEPS_];
        #pragma unroll
        for (int s = 0; s < STEPS_; s++) {
            const float* instr = R + ((size_t)g*STEPS_ + s)*H_;
            float acc = 0.f;
            #pragma unroll
            for (int q = 0; q < 8; q++) {
                int h = lane + 32*q;
                float x = instr[h]*ev[q];
                float el = (x > 0.f) ? x : expm1f(x);
                acc = fmaf(el, wr[q], acc);
            }
            out[s] = warp_sum(acc);
        }
        if (lane == 0)
            *reinterpret_cast<float4*>(es4 + (size_t)e*4) =
                make_float4(out[0], out[1], out[2], out[3]);
    }
}

__global__ void __launch_bounds__(256)
graph_loop_k(const float* __restrict__ ns4, const float* __restrict__ es4,
             const float* __restrict__ ps4,
             const int* __restrict__ esrc, const int* __restrict__ edst,
             float* __restrict__ dist_out) {
    int g = blockIdx.x, tid = threadIdx.x;
    __shared__ float dist[NPG_], agg[NPG_], red[256];
    __shared__ int lsrc[EPG_], ldst[EPG_];
    __shared__ float4 ns[NPG_];

    int nbase = g*NPG_, ebase = g*EPG_;
    for (int e = tid; e < EPG_; e += 256) {
        lsrc[e] = esrc[ebase + e] - nbase;
        ldst[e] = edst[ebase + e] - nbase;
    }
    if (tid < NPG_) {
        dist[tid] = 1.f/(float)NPG_;
        ns[tid] = *reinterpret_cast<const float4*>(ns4 + (size_t)(nbase + tid)*4);
    }
    __syncthreads();

    for (int s = 0; s < STEPS_; s++) {
        if (tid < NPG_) agg[tid] = 0.f;
        __syncthreads();
        for (int e = tid; e < EPG_; e += 256) {
            float sc = es4[(size_t)(ebase + e)*4 + s];
            atomicAdd(&agg[ldst[e]], dist[lsrc[e]]*sc);
        }
        __syncthreads();

        float nsv = (tid < NPG_) ? ((const float*)&ns[tid])[s] : -3.4e38f;
        float agv = (tid < NPG_) ? agg[tid] : -3.4e38f;
        red[tid] = nsv; __syncthreads();
        for (int o = 128; o > 0; o >>= 1) { if (tid < o) red[tid] = fmaxf(red[tid], red[tid+o]); __syncthreads(); }
        float m1 = red[0]; __syncthreads();
        red[tid] = agv; __syncthreads();
        for (int o = 128; o > 0; o >>= 1) { if (tid < o) red[tid] = fmaxf(red[tid], red[tid+o]); __syncthreads(); }
        float m2 = red[0]; __syncthreads();
        float e1 = (tid < NPG_) ? expf(nsv - m1) : 0.f;
        float e2 = (tid < NPG_) ? expf(agv - m2) : 0.f;
        red[tid] = e1; __syncthreads();
        for (int o = 128; o > 0; o >>= 1) { if (tid < o) red[tid] += red[tid+o]; __syncthreads(); }
        float s1 = red[0]; __syncthreads();
        red[tid] = e2; __syncthreads();
        for (int o = 128; o > 0; o >>= 1) { if (tid < o) red[tid] += red[tid+o]; __syncthreads(); }
        float s2 = red[0]; __syncthreads();
        if (tid < NPG_) {
            float r = ps4[((size_t)g*STEPS_ + s)*P_ + 3];
            dist[tid] = r*(e2/s2) + (1.f - r)*(e1/s1);
        }
        __syncthreads();
    }
    if (tid < NPG_) dist_out[nbase + tid] = dist[tid];
}

__global__ void final_agg_qa_k(const float* __restrict__ na, const float* __restrict__ ps4,
                               const float* __restrict__ dist, const __half* __restrict__ Q,
                               __half* __restrict__ QA) {
    int g = blockIdx.x, h = threadIdx.x;
    const float* pp = ps4 + ((size_t)g*STEPS_ + (STEPS_-1))*P_;
    float p0 = pp[0], p1 = pp[1], p2 = pp[2];
    float acc = 0.f;
    for (int i = 0; i < NPG_; i++) {
        size_t n = (size_t)g*NPG_ + i;
        const float* a = na + n*3*H_;
        float nf = p0*a[h] + p1*a[H_+h] + p2*a[2*H_+h];
        acc = fmaf(dist[n], nf, acc);
    }
    QA[(size_t)g*2*H_ + h]      = Q[(size_t)g*H_ + h];
    QA[(size_t)g*2*H_ + H_ + h] = __float2half(acc);
}

// ---------------- launchers ----------------
static inline void gemm_h(cudaStream_t st,
                          const __half* A, int lda, const __half* B, int ldb,
                          void* C, int ldc, int M, int N, int K,
                          const float* bias, int splitk, bool hout) {
    dim3 g((N + 127)/128, (M + 127)/128, splitk);
    if (hout)
        mma_gemm_h<true><<<g, 128, H_SMEM_BYTES, st>>>(A, lda, B, ldb, C, ldc, M, N, K, bias, splitk);
    else
        mma_gemm_h<false><<<g, 128, H_SMEM_BYTES, st>>>(A, lda, B, ldb, C, ldc, M, N, K, bias, splitk);
}
static inline void f2h(cudaStream_t st, const float* s, __half* d, int n) {
    f2h_k<<<(n/4 + 255)/256, 256, 0, st>>>(s, d, n);
}

extern "C" void kernel_launch(void* const* d_in, const int* in_sizes, int n_in,
                              void* d_out, int out_size) {
    const float* questions     = (const float*)d_in[0];
    const float* node_attrs    = (const float*)d_in[1];
    const float* edge_attrs    = (const float*)d_in[2];
    const float* vocab         = (const float*)d_in[3];
    const float* default_embed = (const float*)d_in[4];
    const float* W_norm        = (const float*)d_in[5];
    const float* lstm_Wih      = (const float*)d_in[6];
    const float* lstm_Whh      = (const float*)d_in[7];
    const float* lstm_bih      = (const float*)d_in[8];
    const float* lstm_bhh      = (const float*)d_in[9];
    const float* rnn_Wih       = (const float*)d_in[10];
    const float* rnn_Whh       = (const float*)d_in[11];
    const float* rnn_bih       = (const float*)d_in[12];
    const float* rnn_bhh       = (const float*)d_in[13];
    const float* prop_embeds   = (const float*)d_in[14];
    const float* Ws_property   = (const float*)d_in[15];
    const float* W_state       = (const float*)d_in[16];
    const float* W_relation    = (const float*)d_in[17];
    const float* lin_W         = (const float*)d_in[18];
    const float* lin_b         = (const float*)d_in[19];
    const int*   lengths       = (const int*)d_in[20];
    const int*   node_graph    = (const int*)d_in[21];
    const int*   edge_graph    = (const int*)d_in[22];
    const int*   edge_src      = (const int*)d_in[23];
    const int*   edge_dst      = (const int*)d_in[24];
    float* out = (float*)d_out;

    cudaFuncSetAttribute(mma_gemm_h<false>, cudaFuncAttributeMaxDynamicSharedMemorySize, H_SMEM_BYTES);
    cudaFuncSetAttribute(mma_gemm_h<true>,  cudaFuncAttributeMaxDynamicSharedMemorySize, H_SMEM_BYTES);
    cudaFuncSetAttribute(lstm_mma_h, cudaFuncAttributeMaxDynamicSharedMemorySize, LH_SMEM_BYTES);

    float* S = nullptr;
    cudaGetSymbolAddress((void**)&S, g_scratch);
    __half* CCH  = (__half*)(S + OFF_CCH);
    __half* XWH  = (__half*)(S + OFF_XWH);
    float*  LG   = S + OFF_LOG;
    __half* LGH  = (__half*)(S + OFF_LGH);
    float*  VT   = S + OFF_VT;
    __half* VTH  = (__half*)(S + OFF_VTH);
    float*  XG   = S + OFF_XG;
    __half* H0H  = (__half*)(S + OFF_H0H);
    __half* H1H  = (__half*)(S + OFF_H1H);
    float*  Cst  = S + OFF_CS;
    float*  Rr   = S + OFF_R;
    float*  PS4  = S + OFF_PS;
    float*  TR   = S + OFF_TR;
    float*  ET   = S + OFF_ET;
    float*  NS4  = S + OFF_NS4;
    float*  ES4  = S + OFF_ES4;
    float*  DIST = S + OFF_DIST;
    __half* QAH  = (__half*)(S + OFF_QAH);
    __half* WNTH = (__half*)(S + OFF_WNTH);
    __half* VOCTH= (__half*)(S + OFF_VOCTH);
    float*  WIHT = S + OFF_WIHT;
    float*  WHHT = S + OFF_WHHT;
    __half* QH   = (__half*)(S + OFF_QH);
    __half* WIHH = (__half*)(S + OFF_WIHH);
    __half* WHHH = (__half*)(S + OFF_WHHH);
    __half* NAH  = (__half*)(S + OFF_NAH);
    __half* EAH  = (__half*)(S + OFF_EAH);
    __half* WSH  = (__half*)(S + OFF_WSH);
    __half* LWH  = (__half*)(S + OFF_LWH);

    cudaStream_t s0 = 0;
    cudaStream_t s2;
    cudaEvent_t ev_fork, ev_join;
    cudaStreamCreateWithFlags(&s2, cudaStreamNonBlocking);
    cudaEventCreateWithFlags(&ev_fork, cudaEventDisableTiming);
    cudaEventCreateWithFlags(&ev_join, cudaEventDisableTiming);

    cudaEventRecord(ev_fork, s0);
    cudaStreamWaitEvent(s2, ev_fork, 0);

    // ---- stream 2: fp16 conversions + graph transforms ----
    f2h(s2, node_attrs, NAH, N_*3*H_);
    f2h(s2, edge_attrs, EAH, E_*H_);
    f2h(s2, Ws_property, WSH, P_*H_*H_);
    f2h(s2, lin_W, LWH, OUT_*2*H_);
    for (int p = 0; p < 3; p++)
        gemm_h(s2, NAH + p*H_, 3*H_, WSH + (size_t)p*H_*H_, H_,
               TR + p*H_, 3*H_, N_, H_, H_, nullptr, 1, false);
    gemm_h(s2, EAH, H_, WSH + (size_t)3*H_*H_, H_, ET, H_, E_, H_, H_, nullptr, 1, false);
    cudaEventRecord(ev_join, s2);

    // ---- stream 0: main chain ----
    build_c_h_k<<<((V_+1)*H_ + 255)/256, 256, 0, s0>>>(vocab, default_embed, CCH);
    transpose_h_k<<<dim3(8,8), dim3(32,8), 0, s0>>>(W_norm, WNTH);
    transpose_f_k<<<dim3(8,8), dim3(32,8), 0, s0>>>(rnn_Wih, WIHT);
    transpose_f_k<<<dim3(8,8), dim3(32,8), 0, s0>>>(rnn_Whh, WHHT);
    vocab_t_h_k<<<dim3((LDLOG_+31)/32, H_/32), dim3(32,8), 0, s0>>>(vocab, VOCTH);
    f2h(s0, questions, QH, BL_*H_);
    f2h(s0, lstm_Wih, WIHH, 4*H_*H_);
    f2h(s0, lstm_Whh, WHHH, 4*H_*H_);

    // vocab tagging
    gemm_h(s0, QH, H_, WNTH, H_, XWH, H_, BL_, H_, H_, nullptr, 1, true);
    gemm_h(s0, XWH, H_, CCH, H_, LG, LDLOG_, BL_, V_+1, H_, nullptr, 1, false);
    row_softmax_h_k<<<BL_, 256, 0, s0>>>(LG, LGH);
    vtag_init_k<<<BL_*H_/256, 256, 0, s0>>>(questions, LGH, VT);
    gemm_h(s0, LGH, LDLOG_, VOCTH, LDLOG_, VT, H_, BL_, H_, V_, nullptr, 4, false);
    f2h(s0, VT, VTH, BL_*H_);

    // LSTM encoder
    gemm_h(s0, VTH, H_, WIHH, H_, XG, 4*H_, BL_, 4*H_, H_, lstm_bih, 1, false);
    zero_k<<<(B_*H_/2 + 255)/256, 256, 0, s0>>>(S + OFF_H0H, B_*H_/2);   // H0H = 0
    zero_k<<<(B_*H_ + 255)/256, 256, 0, s0>>>(Cst, B_*H_);
    for (int t = 0; t < L_; t++) {
        const __half* hin = (t & 1) ? H1H : H0H;
        __half* hout      = (t & 1) ? H0H : H1H;
        lstm_mma_h<<<dim3(H_/32, B_/64), 128, LH_SMEM_BYTES, s0>>>(hin, hout, Cst, XG,
                                                                   WHHH, lstm_bhh, lengths, t);
    }

    // decoder + attention + prop softmax
    dec_attn_k<<<B_, 256, 0, s0>>>(H0H, WIHT, WHHT, rnn_bih, rnn_bhh, VT, lengths, Rr);
    prop_all_k<<<dim3(B_, STEPS_), 128, 0, s0>>>(Rr, prop_embeds, PS4);

    // join transforms, then reasoning
    cudaStreamWaitEvent(s0, ev_join, 0);
    scores_k<<<NODE_BLKS + EDGE_BLKS, 256, 0, s0>>>(TR, ET, Rr, PS4, W_state, W_relation,
                                                    node_graph, edge_graph, NS4, ES4);
    graph_loop_k<<<B_, 256, 0, s0>>>(NS4, ES4, PS4, edge_src, edge_dst, DIST);

    // final aggregation + output projection
    final_agg_qa_k<<<B_, 256, 0, s0>>>(node_attrs, PS4, DIST, H0H, QAH);
    zero_k<<<(B_*OUT_ + 255)/256, 256, 0, s0>>>(out, B_*OUT_);
    gemm_h(s0, QAH, 2*H_, LWH, 2*H_, out, OUT_, B_, OUT_, 2*H_, lin_b, 4, false);

    cudaStreamDestroy(s2);
    cudaEventDestroy(ev_fork);
    cudaEventDestroy(ev_join);
}